// round 14
// baseline (speedup 1.0000x reference)
#include <cuda_runtime.h>
#include <cuda_bf16.h>
#include <math.h>
#include <stdint.h>

#define BATCH 8
#define NNODE 20000
#define FEATD 256
#define HDIM  512
#define HCW   4096
#define F1D   1024
#define KO1   32
#define KO2   10
#define EPSBN 1e-5f
#define KCHUNKS 8
#define MBLK ((NNODE + 127) / 128)      // 157 m-blocks

typedef __nv_bfloat16 bf16;

// ---------------- scratch ----------------
__device__ __align__(16) float g_h1[(size_t)BATCH * NNODE * HDIM];
__device__ __align__(16) float g_hc[(size_t)NNODE * HCW];
__device__ __align__(16) float g_f [(size_t)NNODE * F1D];
__device__ __align__(16) float g_f2[(size_t)NNODE * KO1];
__device__ __align__(16) float g_kpart[(size_t)KCHUNKS * KO1 * NNODE];

__device__ __align__(16) bf16 g_xhi[(size_t)BATCH * NNODE * FEATD];
__device__ __align__(16) bf16 g_xlo[(size_t)BATCH * NNODE * FEATD];
__device__ __align__(16) bf16 g_h1hi[(size_t)BATCH * NNODE * HDIM];
__device__ __align__(16) bf16 g_h1lo[(size_t)BATCH * NNODE * HDIM];
__device__ __align__(16) bf16 g_hchi[(size_t)NNODE * HCW];
__device__ __align__(16) bf16 g_hclo[(size_t)NNODE * HCW];
__device__ __align__(16) bf16 g_w1hi[(size_t)BATCH * HDIM * FEATD];
__device__ __align__(16) bf16 g_w1lo[(size_t)BATCH * HDIM * FEATD];
__device__ __align__(16) bf16 g_w2hi[(size_t)BATCH * HDIM * HDIM];
__device__ __align__(16) bf16 g_w2lo[(size_t)BATCH * HDIM * HDIM];
__device__ __align__(16) bf16 g_wfhi[(size_t)F1D * HCW];
__device__ __align__(16) bf16 g_wflo[(size_t)F1D * HCW];

__device__ float2 g_part[(size_t)MBLK * HCW];    // per-m-block column stats partials
__device__ float  g_scale1[HCW], g_shift1[HCW];
__device__ float  g_scale2[HCW], g_shift2[HCW];

// ================= PTX helpers (compute_103-safe) =================
__device__ __forceinline__ uint32_t smem_u32(const void* p) {
    uint32_t a;
    asm("{ .reg .u64 t; cvta.to.shared.u64 t, %1; cvt.u32.u64 %0, t; }" : "=r"(a) : "l"(p));
    return a;
}
__device__ __forceinline__ void cpa16(uint32_t dst, const void* src, bool pred) {
    int sz = pred ? 16 : 0;
    asm volatile("cp.async.cg.shared.global [%0], [%1], 16, %2;" :: "r"(dst), "l"(src), "r"(sz) : "memory");
}
__device__ __forceinline__ void cpa_commit() { asm volatile("cp.async.commit_group;" ::: "memory"); }
__device__ __forceinline__ void cpa_wait2() { asm volatile("cp.async.wait_group 2;" ::: "memory"); }
__device__ __forceinline__ void cpa_wait0() { asm volatile("cp.async.wait_group 0;" ::: "memory"); }

__device__ __forceinline__ void ldsm_x4(uint32_t& r0, uint32_t& r1, uint32_t& r2, uint32_t& r3, uint32_t addr) {
    asm volatile("ldmatrix.sync.aligned.m8n8.x4.shared.b16 {%0,%1,%2,%3}, [%4];"
                 : "=r"(r0), "=r"(r1), "=r"(r2), "=r"(r3) : "r"(addr));
}
__device__ __forceinline__ void mma16816(float* c, uint32_t a0, uint32_t a1, uint32_t a2, uint32_t a3,
                                         uint32_t b0, uint32_t b1) {
    asm volatile("mma.sync.aligned.m16n8k16.row.col.f32.bf16.bf16.f32 "
                 "{%0,%1,%2,%3}, {%4,%5,%6,%7}, {%8,%9}, {%0,%1,%2,%3};"
                 : "+f"(c[0]), "+f"(c[1]), "+f"(c[2]), "+f"(c[3])
                 : "r"(a0), "r"(a1), "r"(a2), "r"(a3), "r"(b0), "r"(b1));
}
static __device__ __forceinline__ uint32_t sw128(uint32_t off) { return off ^ ((off >> 3) & 0x70); }

// ================= HMMA GEMM — round-13 core + fused BN-stats epilogue =================
#define GTHREADS 256
#define KC 64
#define STAGE_BYTES 65536
#define NSTAGE 3
#define GEMM_SMEM (NSTAGE * STAGE_BYTES + 1024)

__global__ void __launch_bounds__(GTHREADS)
gemm_mma_kernel(const bf16* __restrict__ Ahi, const bf16* __restrict__ Alo, long aBatch,
                const bf16* __restrict__ Bhi, const bf16* __restrict__ Blo, long bBatch,
                const float* __restrict__ bias, long biasBatch,
                float* __restrict__ C, long cBatch, int ldc,
                float2* __restrict__ statPart, long statBzStride,
                int M, int K, int reluEpi)
{
    extern __shared__ char smem[];
    const uint32_t S = (smem_u32(smem) + 1023) & ~1023u;

    const int bz = blockIdx.z;
    Ahi += (long)bz * aBatch;  Alo += (long)bz * aBatch;
    Bhi += (long)bz * bBatch;  Blo += (long)bz * bBatch;
    const float* bp = bias + (long)bz * biasBatch;
    C += (long)bz * cBatch;

    const int n0 = blockIdx.x * 128;
    const int m0 = blockIdx.y * 128;
    const int t  = threadIdx.x;
    const int wid = t >> 5, lid = t & 31;
    const int warp_m = wid & 3;
    const int warp_n = wid >> 2;
    const int T = K / KC;

    auto load_tile = [&](int kt, int stg) {
        const uint32_t sb = S + stg * STAGE_BYTES;
        const int kbase = kt * KC;
#pragma unroll
        for (int j = 0; j < 4; j++) {
            int cid = t + j * 256;
            int row = cid >> 3, c16 = cid & 7;
            uint32_t dsw = sw128((uint32_t)(row * 128 + c16 * 16));
            size_t aoff = (size_t)(m0 + row) * K + kbase + c16 * 8;
            bool ap = (m0 + row) < M;
            cpa16(sb + dsw,          Ahi + aoff, ap);
            cpa16(sb + 16384 + dsw,  Alo + aoff, ap);
            size_t boff = (size_t)(n0 + row) * K + kbase + c16 * 8;
            cpa16(sb + 32768 + dsw,  Bhi + boff, true);
            cpa16(sb + 49152 + dsw,  Blo + boff, true);
        }
        cpa_commit();
    };

    float acc[2][8][4];
#pragma unroll
    for (int i = 0; i < 2; i++)
#pragma unroll
        for (int j = 0; j < 8; j++)
#pragma unroll
            for (int q = 0; q < 4; q++) acc[i][j][q] = 0.f;

#pragma unroll
    for (int p = 0; p < NSTAGE; p++) {
        if (p < T) load_tile(p, p); else cpa_commit();
    }

    const int lrow = lid & 15;
    const int lhalf = (lid >> 4) * 16;

    uint32_t ah[2][2][4], al[2][2][4], bh[2][4][4], bl[2][4][4];

#define LOAD_FRAGS(buf, kb, sb)                                                   \
    {                                                                             \
        _Pragma("unroll")                                                         \
        for (int mf = 0; mf < 2; mf++) {                                          \
            int row = warp_m * 32 + mf * 16 + lrow;                               \
            uint32_t off = sw128((uint32_t)(row * 128 + (kb) + lhalf));           \
            ldsm_x4(ah[buf][mf][0], ah[buf][mf][1], ah[buf][mf][2], ah[buf][mf][3], (sb) + off);          \
            ldsm_x4(al[buf][mf][0], al[buf][mf][1], al[buf][mf][2], al[buf][mf][3], (sb) + 16384 + off);  \
        }                                                                         \
        _Pragma("unroll")                                                         \
        for (int g = 0; g < 4; g++) {                                             \
            int row = warp_n * 64 + g * 16 + lrow;                                \
            uint32_t off = sw128((uint32_t)(row * 128 + (kb) + lhalf));           \
            ldsm_x4(bh[buf][g][0], bh[buf][g][1], bh[buf][g][2], bh[buf][g][3], (sb) + 32768 + off);      \
            ldsm_x4(bl[buf][g][0], bl[buf][g][1], bl[buf][g][2], bl[buf][g][3], (sb) + 49152 + off);      \
        }                                                                         \
    }

    for (int kt = 0; kt < T; kt++) {
        cpa_wait2();
        __syncthreads();
        const uint32_t sb = S + (kt % NSTAGE) * STAGE_BYTES;

        LOAD_FRAGS(0, 0, sb);

#pragma unroll
        for (int kk = 0; kk < 4; kk++) {
            const int cur = kk & 1;
            if (kk < 3) {
                const int nb = (kk + 1) * 32;
                LOAD_FRAGS(cur ^ 1, nb, sb);
            }
#pragma unroll
            for (int mf = 0; mf < 2; mf++) {
#pragma unroll
                for (int nf = 0; nf < 8; nf++) {
                    int g = nf >> 1, od = nf & 1;
                    mma16816(acc[mf][nf], ah[cur][mf][0], ah[cur][mf][1], ah[cur][mf][2], ah[cur][mf][3],
                             od ? bh[cur][g][1] : bh[cur][g][0], od ? bh[cur][g][3] : bh[cur][g][2]);
                }
#pragma unroll
                for (int nf = 0; nf < 8; nf++) {
                    int g = nf >> 1, od = nf & 1;
                    mma16816(acc[mf][nf], ah[cur][mf][0], ah[cur][mf][1], ah[cur][mf][2], ah[cur][mf][3],
                             od ? bl[cur][g][1] : bl[cur][g][0], od ? bl[cur][g][3] : bl[cur][g][2]);
                }
#pragma unroll
                for (int nf = 0; nf < 8; nf++) {
                    int g = nf >> 1, od = nf & 1;
                    mma16816(acc[mf][nf], al[cur][mf][0], al[cur][mf][1], al[cur][mf][2], al[cur][mf][3],
                             od ? bh[cur][g][1] : bh[cur][g][0], od ? bh[cur][g][3] : bh[cur][g][2]);
                }
            }
        }
        __syncthreads();
        if (kt + NSTAGE < T) load_tile(kt + NSTAGE, kt % NSTAGE); else cpa_commit();
    }
    cpa_wait0();
#undef LOAD_FRAGS

    // ---- epilogue: bias (+relu), C stores, and fused column stats partials ----
    float sc16[16], qc16[16];
#pragma unroll
    for (int i = 0; i < 16; i++) { sc16[i] = 0.f; qc16[i] = 0.f; }

#pragma unroll
    for (int mf = 0; mf < 2; mf++) {
        int rbase = m0 + warp_m * 32 + mf * 16 + (lid >> 2);
        bool ok0 = rbase < M, ok1 = rbase + 8 < M;
#pragma unroll
        for (int nf = 0; nf < 8; nf++) {
            int col = n0 + warp_n * 64 + nf * 8 + (lid & 3) * 2;
            float bx = __ldg(&bp[col]), by = __ldg(&bp[col + 1]);
            float v0 = acc[mf][nf][0] + bx, v1 = acc[mf][nf][1] + by;
            float v2 = acc[mf][nf][2] + bx, v3 = acc[mf][nf][3] + by;
            if (reluEpi) {
                v0 = fmaxf(v0, 0.f); v1 = fmaxf(v1, 0.f);
                v2 = fmaxf(v2, 0.f); v3 = fmaxf(v3, 0.f);
            }
            if (ok0) *(float2*)&C[(size_t)rbase * ldc + col]       = make_float2(v0, v1);
            if (ok1) *(float2*)&C[(size_t)(rbase + 8) * ldc + col] = make_float2(v2, v3);
            if (statPart) {
                float a0 = ok0 ? v0 : 0.f, a1 = ok0 ? v1 : 0.f;
                float a2 = ok1 ? v2 : 0.f, a3 = ok1 ? v3 : 0.f;
                sc16[nf * 2 + 0] += a0 + a2;
                qc16[nf * 2 + 0] += a0 * a0 + a2 * a2;
                sc16[nf * 2 + 1] += a1 + a3;
                qc16[nf * 2 + 1] += a1 * a1 + a3 * a3;
            }
        }
    }

    if (statPart) {
        // reduce over the 8 lanes sharing each column (bits 2..4 of lane id)
#pragma unroll
        for (int i = 0; i < 16; i++) {
#pragma unroll
            for (int off = 4; off <= 16; off <<= 1) {
                sc16[i] += __shfl_xor_sync(0xffffffffu, sc16[i], off);
                qc16[i] += __shfl_xor_sync(0xffffffffu, qc16[i], off);
            }
        }
        float2* red = (float2*)smem;                  // stage buffers idle now
        if (lid < 4) {
#pragma unroll
            for (int nf = 0; nf < 8; nf++)
#pragma unroll
                for (int b = 0; b < 2; b++) {
                    int col = warp_n * 64 + nf * 8 + lid * 2 + b;
                    red[warp_m * 128 + col] = make_float2(sc16[nf * 2 + b], qc16[nf * 2 + b]);
                }
        }
        __syncthreads();
        if (t < 128) {
            float s = 0.f, q = 0.f;
#pragma unroll
            for (int wm = 0; wm < 4; wm++) {
                float2 p = red[wm * 128 + t];
                s += p.x; q += p.y;
            }
            statPart[(size_t)blockIdx.y * HCW + (size_t)bz * statBzStride + n0 + t] = make_float2(s, q);
        }
    }
}

// ================= split / transpose kernels =================
__global__ void split_kernel(const float* __restrict__ in, bf16* __restrict__ hi,
                             bf16* __restrict__ lo, size_t n)
{
    size_t i = ((size_t)blockIdx.x * blockDim.x + threadIdx.x) * 4;
    if (i >= n) return;
    float4 v = *(const float4*)(in + i);
    bf16 h0 = __float2bfloat16(v.x), h1 = __float2bfloat16(v.y);
    bf16 h2 = __float2bfloat16(v.z), h3 = __float2bfloat16(v.w);
    hi[i] = h0; hi[i+1] = h1; hi[i+2] = h2; hi[i+3] = h3;
    lo[i]   = __float2bfloat16(v.x - __bfloat162float(h0));
    lo[i+1] = __float2bfloat16(v.y - __bfloat162float(h1));
    lo[i+2] = __float2bfloat16(v.z - __bfloat162float(h2));
    lo[i+3] = __float2bfloat16(v.w - __bfloat162float(h3));
}

__global__ void split_affine_kernel(const float* __restrict__ in,
                                    const float* __restrict__ sc, const float* __restrict__ sh,
                                    int ld, bf16* __restrict__ hi, bf16* __restrict__ lo, size_t n)
{
    size_t i = ((size_t)blockIdx.x * blockDim.x + threadIdx.x) * 4;
    if (i >= n) return;
    float4 v = *(const float4*)(in + i);
    int col = (int)(i % ld);
    int soff = (int)(i / ((size_t)ld * NNODE)) * ld + col;
    float4 s = *(const float4*)(sc + soff);
    float4 h = *(const float4*)(sh + soff);
    float w0 = fmaxf(fmaf(v.x, s.x, h.x), 0.f);
    float w1 = fmaxf(fmaf(v.y, s.y, h.y), 0.f);
    float w2 = fmaxf(fmaf(v.z, s.z, h.z), 0.f);
    float w3 = fmaxf(fmaf(v.w, s.w, h.w), 0.f);
    bf16 a0 = __float2bfloat16(w0), a1 = __float2bfloat16(w1);
    bf16 a2 = __float2bfloat16(w2), a3 = __float2bfloat16(w3);
    hi[i] = a0; hi[i+1] = a1; hi[i+2] = a2; hi[i+3] = a3;
    lo[i]   = __float2bfloat16(w0 - __bfloat162float(a0));
    lo[i+1] = __float2bfloat16(w1 - __bfloat162float(a1));
    lo[i+2] = __float2bfloat16(w2 - __bfloat162float(a2));
    lo[i+3] = __float2bfloat16(w3 - __bfloat162float(a3));
}

__global__ void tsplit_kernel(const float* __restrict__ W, long wBatch, int K, int Nn,
                              bf16* __restrict__ hi, bf16* __restrict__ lo, long oBatch)
{
    __shared__ float tile[32][33];
    const float* Wb = W + (long)blockIdx.z * wBatch;
    bf16* hib = hi + (long)blockIdx.z * oBatch;
    bf16* lob = lo + (long)blockIdx.z * oBatch;
    int nb = blockIdx.x * 32, kb = blockIdx.y * 32;
    int tx = threadIdx.x, ty = threadIdx.y;
#pragma unroll
    for (int r = 0; r < 32; r += 8)
        tile[ty + r][tx] = Wb[(size_t)(kb + ty + r) * Nn + nb + tx];
    __syncthreads();
#pragma unroll
    for (int r = 0; r < 32; r += 8) {
        float v = tile[tx][ty + r];
        bf16 h = __float2bfloat16(v);
        size_t o = (size_t)(nb + ty + r) * K + kb + tx;
        hib[o] = h;
        lob[o] = __float2bfloat16(v - __bfloat162float(h));
    }
}

// ================= BN finalize (reduces per-m-block partials) =================
__global__ void finalize_bn_kernel(const float2* __restrict__ part,
                                   const float* __restrict__ g, const float* __restrict__ be,
                                   float* __restrict__ sc, float* __restrict__ sh, float invN)
{
    int i = blockIdx.x * blockDim.x + threadIdx.x;
    float s = 0.f, q = 0.f;
    for (int r = 0; r < MBLK; r++) {
        float2 p = part[(size_t)r * HCW + i];
        s += p.x; q += p.y;
    }
    float mu  = s * invN;
    float var = q * invN - mu * mu;
    float sl = g[i] * rsqrtf(var + EPSBN);
    sc[i] = sl;
    sh[i] = be[i] - mu * sl;
}

// ================= KAN =================
__device__ __forceinline__ void bspline8(float x, float bs[11])
{
#pragma unroll
    for (int j = 0; j < 11; j++) {
        float gl = (float)(j - 3) * 0.4f - 1.0f;
        float gr = (float)(j - 2) * 0.4f - 1.0f;
        bs[j] = (x >= gl && x < gr) ? 1.0f : 0.0f;
    }
#pragma unroll
    for (int p = 1; p <= 3; p++) {
        float inv = 1.0f / (0.4f * (float)p);
#pragma unroll
        for (int j = 0; j < 11 - p; j++) {
            float gj   = (float)(j - 3) * 0.4f - 1.0f;
            float gjp1 = (float)(j + p - 2) * 0.4f - 1.0f;
            bs[j] = ((x - gj) * bs[j] + (gjp1 - x) * bs[j + 1]) * inv;
        }
    }
}

__global__ void __launch_bounds__(256)
kan1_part_kernel(const float* __restrict__ X, const float* __restrict__ bw,
                 const float* __restrict__ sw, const float* __restrict__ sc,
                 float* __restrict__ part, int n)
{
    int node = blockIdx.x * blockDim.x + threadIdx.x;
    int chunk = blockIdx.y;
    if (node >= n) return;
    float acc[KO1];
#pragma unroll
    for (int o = 0; o < KO1; o++) acc[o] = 0.f;

    const int i0 = chunk * (F1D / KCHUNKS);
    for (int ii = 0; ii < F1D / KCHUNKS; ii++) {
        int i = i0 + ii;
        float x = __ldg(&X[(size_t)node * F1D + i]);
        float bs[11];
        bspline8(x, bs);
        float s = x / (1.0f + expf(-x));
#pragma unroll 8
        for (int o = 0; o < KO1; o++) {
            const float4* swp = (const float4*)(sw + ((size_t)o * F1D + i) * 8);
            float4 w0 = __ldg(&swp[0]);
            float4 w1 = __ldg(&swp[1]);
            float sp = bs[0] * w0.x + bs[1] * w0.y + bs[2] * w0.z + bs[3] * w0.w
                     + bs[4] * w1.x + bs[5] * w1.y + bs[6] * w1.z + bs[7] * w1.w;
            acc[o] = fmaf(s, __ldg(&bw[(size_t)o * F1D + i]),
                     fmaf(sp, __ldg(&sc[(size_t)o * F1D + i]), acc[o]));
        }
    }
#pragma unroll
    for (int o = 0; o < KO1; o++)
        part[((size_t)chunk * KO1 + o) * n + node] = acc[o];
}

__global__ void kan1_reduce_kernel(const float* __restrict__ part, float* __restrict__ out, int n)
{
    int gid = blockIdx.x * blockDim.x + threadIdx.x;
    if (gid >= n * KO1) return;
    int node = gid >> 5, o = gid & 31;
    float s = 0.f;
#pragma unroll
    for (int c = 0; c < KCHUNKS; c++)
        s += part[((size_t)c * KO1 + o) * n + node];
    out[(size_t)node * KO1 + o] = s;
}

template <int IN, int OUTC>
__global__ void __launch_bounds__(128)
kan_kernel(const float* __restrict__ X, const float* __restrict__ bw,
           const float* __restrict__ sw, const float* __restrict__ sc,
           float* __restrict__ out, int n)
{
    int node = blockIdx.x * blockDim.x + threadIdx.x;
    if (node >= n) return;
    float acc[OUTC];
#pragma unroll
    for (int o = 0; o < OUTC; o++) acc[o] = 0.f;

    for (int i = 0; i < IN; i++) {
        float x = __ldg(&X[(size_t)node * IN + i]);
        float bs[11];
        bspline8(x, bs);
        float s = x / (1.0f + expf(-x));
#pragma unroll
        for (int o = 0; o < OUTC; o++) {
            const float4* swp = (const float4*)(sw + ((size_t)o * IN + i) * 8);
            float4 w0 = __ldg(&swp[0]);
            float4 w1 = __ldg(&swp[1]);
            float sp = bs[0] * w0.x + bs[1] * w0.y + bs[2] * w0.z + bs[3] * w0.w
                     + bs[4] * w1.x + bs[5] * w1.y + bs[6] * w1.z + bs[7] * w1.w;
            acc[o] = fmaf(s, __ldg(&bw[(size_t)o * IN + i]),
                     fmaf(sp, __ldg(&sc[(size_t)o * IN + i]), acc[o]));
        }
    }
#pragma unroll
    for (int o = 0; o < OUTC; o++) out[(size_t)node * OUTC + o] = acc[o];
}

// ================= launch =================
extern "C" void kernel_launch(void* const* d_in, const int* in_sizes, int n_in,
                              void* d_out, int out_size)
{
    const float* x   = (const float*)d_in[0];
    const float* W1  = (const float*)d_in[3];
    const float* b1  = (const float*)d_in[4];
    const float* gm1 = (const float*)d_in[5];
    const float* bt1 = (const float*)d_in[6];
    const float* W2  = (const float*)d_in[7];
    const float* b2  = (const float*)d_in[8];
    const float* gm2 = (const float*)d_in[9];
    const float* bt2 = (const float*)d_in[10];
    const float* Wf  = (const float*)d_in[11];
    const float* bf  = (const float*)d_in[12];
    const float* bw1 = (const float*)d_in[13];
    const float* sw1 = (const float*)d_in[14];
    const float* sc1 = (const float*)d_in[15];
    const float* bw2 = (const float*)d_in[16];
    const float* sw2 = (const float*)d_in[17];
    const float* sc2 = (const float*)d_in[18];

    float *h1, *hc, *f, *f2, *sca1, *shf1, *sca2, *shf2, *kpart;
    float2 *part;
    bf16 *xhi, *xlo, *h1hi, *h1lo, *hchi, *hclo, *w1hi, *w1lo, *w2hi, *w2lo, *wfhi, *wflo;
    cudaGetSymbolAddress((void**)&h1, g_h1);   cudaGetSymbolAddress((void**)&hc, g_hc);
    cudaGetSymbolAddress((void**)&f, g_f);     cudaGetSymbolAddress((void**)&f2, g_f2);
    cudaGetSymbolAddress((void**)&kpart, g_kpart);
    cudaGetSymbolAddress((void**)&xhi, g_xhi); cudaGetSymbolAddress((void**)&xlo, g_xlo);
    cudaGetSymbolAddress((void**)&h1hi, g_h1hi); cudaGetSymbolAddress((void**)&h1lo, g_h1lo);
    cudaGetSymbolAddress((void**)&hchi, g_hchi); cudaGetSymbolAddress((void**)&hclo, g_hclo);
    cudaGetSymbolAddress((void**)&w1hi, g_w1hi); cudaGetSymbolAddress((void**)&w1lo, g_w1lo);
    cudaGetSymbolAddress((void**)&w2hi, g_w2hi); cudaGetSymbolAddress((void**)&w2lo, g_w2lo);
    cudaGetSymbolAddress((void**)&wfhi, g_wfhi); cudaGetSymbolAddress((void**)&wflo, g_wflo);
    cudaGetSymbolAddress((void**)&part, g_part);
    cudaGetSymbolAddress((void**)&sca1, g_scale1); cudaGetSymbolAddress((void**)&shf1, g_shift1);
    cudaGetSymbolAddress((void**)&sca2, g_scale2); cudaGetSymbolAddress((void**)&shf2, g_shift2);

    cudaFuncSetAttribute(gemm_mma_kernel, cudaFuncAttributeMaxDynamicSharedMemorySize, GEMM_SMEM);

    dim3 tb(32, 8);

    // 1: x -> hi/lo
    {
        size_t n = (size_t)BATCH * NNODE * FEATD;
        split_kernel<<<(unsigned)((n/4 + 255)/256), 256>>>(x, xhi, xlo, n);
    }
    // 2-3: W1, W2 transpose+split
    tsplit_kernel<<<dim3(HDIM/32, FEATD/32, BATCH), tb>>>(W1, (long)FEATD*HDIM, FEATD, HDIM, w1hi, w1lo, (long)HDIM*FEATD);
    tsplit_kernel<<<dim3(HDIM/32, HDIM/32, BATCH), tb>>>(W2, (long)HDIM*HDIM, HDIM, HDIM, w2hi, w2lo, (long)HDIM*HDIM);

    // 4: GEMM1 (+ fused BN1 stats partials)
    gemm_mma_kernel<<<dim3(HDIM/128, MBLK, BATCH), GTHREADS, GEMM_SMEM>>>(
        xhi, xlo, (long)NNODE*FEATD, w1hi, w1lo, (long)HDIM*FEATD,
        b1, HDIM, h1, (long)NNODE*HDIM, HDIM,
        part, HDIM, NNODE, FEATD, 0);

    // 5: Wf transpose+split (independent; overlaps BN1 chain)
    tsplit_kernel<<<dim3(F1D/32, HCW/32, 1), tb>>>(Wf, 0, HCW, F1D, wfhi, wflo, 0);

    // BN1 finalize + affine split
    finalize_bn_kernel<<<HCW/256, 256>>>(part, gm1, bt1, sca1, shf1, 1.0f/NNODE);
    {
        size_t n = (size_t)BATCH * NNODE * HDIM;
        split_affine_kernel<<<(unsigned)((n/4 + 255)/256), 256>>>(h1, sca1, shf1, HDIM, h1hi, h1lo, n);
    }

    // GEMM2 (+ fused BN2 stats partials)
    gemm_mma_kernel<<<dim3(HDIM/128, MBLK, BATCH), GTHREADS, GEMM_SMEM>>>(
        h1hi, h1lo, (long)NNODE*HDIM, w2hi, w2lo, (long)HDIM*HDIM,
        b2, HDIM, hc, (long)HDIM, HCW,
        part, HDIM, NNODE, HDIM, 0);

    // BN2 finalize + affine split
    finalize_bn_kernel<<<HCW/256, 256>>>(part, gm2, bt2, sca2, shf2, 1.0f/NNODE);
    {
        size_t n = (size_t)NNODE * HCW;
        split_affine_kernel<<<(unsigned)((n/4 + 255)/256), 256>>>(hc, sca2, shf2, HCW, hchi, hclo, n);
    }

    // GEMM3 (no stats)
    gemm_mma_kernel<<<dim3(F1D/128, MBLK, 1), GTHREADS, GEMM_SMEM>>>(
        hchi, hclo, 0, wfhi, wflo, 0,
        bf, 0, f, 0, F1D,
        nullptr, 0, NNODE, HCW, 1);

    // KAN layer 1: chunked partials + deterministic reduce
    kan1_part_kernel<<<dim3((NNODE + 255)/256, KCHUNKS), 256>>>(f, bw1, sw1, sc1, kpart, NNODE);
    kan1_reduce_kernel<<<(NNODE * KO1 + 255)/256, 256>>>(kpart, f2, NNODE);

    // KAN layer 2
    kan_kernel<KO1, KO2><<<(NNODE + 127)/128, 128>>>(f2, bw2, sw2, sc2, (float*)d_out, NNODE);
}

// round 15
// speedup vs baseline: 1.0018x; 1.0018x over previous
#include <cuda_runtime.h>
#include <cuda_bf16.h>
#include <math.h>
#include <stdint.h>

#define BATCH 8
#define NNODE 20000
#define FEATD 256
#define HDIM  512
#define HCW   4096
#define F1D   1024
#define KO1   32
#define KO2   10
#define EPSBN 1e-5f
#define KCHUNKS 8
#define BMT 256
#define MBLK ((NNODE + BMT - 1) / BMT)      // 79 m-blocks

typedef __nv_bfloat16 bf16;

// ---------------- scratch ----------------
__device__ __align__(16) float g_h1[(size_t)BATCH * NNODE * HDIM];
__device__ __align__(16) float g_hc[(size_t)NNODE * HCW];
__device__ __align__(16) float g_f [(size_t)NNODE * F1D];
__device__ __align__(16) float g_f2[(size_t)NNODE * KO1];
__device__ __align__(16) float g_kpart[(size_t)KCHUNKS * KO1 * NNODE];

__device__ __align__(16) bf16 g_xhi[(size_t)BATCH * NNODE * FEATD];
__device__ __align__(16) bf16 g_xlo[(size_t)BATCH * NNODE * FEATD];
__device__ __align__(16) bf16 g_h1hi[(size_t)BATCH * NNODE * HDIM];
__device__ __align__(16) bf16 g_h1lo[(size_t)BATCH * NNODE * HDIM];
__device__ __align__(16) bf16 g_hchi[(size_t)NNODE * HCW];
__device__ __align__(16) bf16 g_hclo[(size_t)NNODE * HCW];
__device__ __align__(16) bf16 g_w1hi[(size_t)BATCH * HDIM * FEATD];
__device__ __align__(16) bf16 g_w1lo[(size_t)BATCH * HDIM * FEATD];
__device__ __align__(16) bf16 g_w2hi[(size_t)BATCH * HDIM * HDIM];
__device__ __align__(16) bf16 g_w2lo[(size_t)BATCH * HDIM * HDIM];
__device__ __align__(16) bf16 g_wfhi[(size_t)F1D * HCW];
__device__ __align__(16) bf16 g_wflo[(size_t)F1D * HCW];

__device__ float2 g_part[(size_t)MBLK * HCW];
__device__ float  g_scale1[HCW], g_shift1[HCW];
__device__ float  g_scale2[HCW], g_shift2[HCW];

// ================= PTX helpers (compute_103-safe) =================
__device__ __forceinline__ uint32_t smem_u32(const void* p) {
    uint32_t a;
    asm("{ .reg .u64 t; cvta.to.shared.u64 t, %1; cvt.u32.u64 %0, t; }" : "=r"(a) : "l"(p));
    return a;
}
__device__ __forceinline__ void cpa16(uint32_t dst, const void* src, bool pred) {
    int sz = pred ? 16 : 0;
    asm volatile("cp.async.cg.shared.global [%0], [%1], 16, %2;" :: "r"(dst), "l"(src), "r"(sz) : "memory");
}
__device__ __forceinline__ void cpa_commit() { asm volatile("cp.async.commit_group;" ::: "memory"); }
__device__ __forceinline__ void cpa_wait1() { asm volatile("cp.async.wait_group 1;" ::: "memory"); }
__device__ __forceinline__ void cpa_wait0() { asm volatile("cp.async.wait_group 0;" ::: "memory"); }

__device__ __forceinline__ void ldsm_x4(uint32_t& r0, uint32_t& r1, uint32_t& r2, uint32_t& r3, uint32_t addr) {
    asm volatile("ldmatrix.sync.aligned.m8n8.x4.shared.b16 {%0,%1,%2,%3}, [%4];"
                 : "=r"(r0), "=r"(r1), "=r"(r2), "=r"(r3) : "r"(addr));
}
__device__ __forceinline__ void mma16816(float* c, uint32_t a0, uint32_t a1, uint32_t a2, uint32_t a3,
                                         uint32_t b0, uint32_t b1) {
    asm volatile("mma.sync.aligned.m16n8k16.row.col.f32.bf16.bf16.f32 "
                 "{%0,%1,%2,%3}, {%4,%5,%6,%7}, {%8,%9}, {%0,%1,%2,%3};"
                 : "+f"(c[0]), "+f"(c[1]), "+f"(c[2]), "+f"(c[3])
                 : "r"(a0), "r"(a1), "r"(a2), "r"(a3), "r"(b0), "r"(b1));
}
static __device__ __forceinline__ uint32_t sw128(uint32_t off) { return off ^ ((off >> 3) & 0x70); }

// ================= HMMA GEMM — CTA 256x128, warp tile 64x64 =================
// 8 warps: warp_m = wid&3 (4 x 64 rows), warp_n = wid>>2 (2 x 64 cols).
// Per kk16: 16 LDSM -> 96 MMA (ratio 6). Stage 96KB, NSTAGE 2 -> 192KB smem.
#define GTHREADS 256
#define KC 64
#define STAGE_BYTES 98304
#define NSTAGE 2
#define GEMM_SMEM (NSTAGE * STAGE_BYTES + 1024)
#define OFF_ALO 32768
#define OFF_BHI 65536
#define OFF_BLO 81920

__global__ void __launch_bounds__(GTHREADS, 1)
gemm_mma_kernel(const bf16* __restrict__ Ahi, const bf16* __restrict__ Alo, long aBatch,
                const bf16* __restrict__ Bhi, const bf16* __restrict__ Blo, long bBatch,
                const float* __restrict__ bias, long biasBatch,
                float* __restrict__ C, long cBatch, int ldc,
                float2* __restrict__ statPart, long statBzStride,
                int M, int K, int reluEpi)
{
    extern __shared__ char smem[];
    const uint32_t S = (smem_u32(smem) + 1023) & ~1023u;

    const int bz = blockIdx.z;
    Ahi += (long)bz * aBatch;  Alo += (long)bz * aBatch;
    Bhi += (long)bz * bBatch;  Blo += (long)bz * bBatch;
    const float* bp = bias + (long)bz * biasBatch;
    C += (long)bz * cBatch;

    const int n0 = blockIdx.x * 128;
    const int m0 = blockIdx.y * BMT;
    const int t  = threadIdx.x;
    const int wid = t >> 5, lid = t & 31;
    const int warp_m = wid & 3;           // 4 x 64 rows
    const int warp_n = wid >> 2;          // 2 x 64 cols
    const int T = K / KC;

    auto load_tile = [&](int kt, int stg) {
        const uint32_t sb = S + stg * STAGE_BYTES;
        const int kbase = kt * KC;
        // A: 256 rows x 128B, two arrays (2048 16B chunks each)
#pragma unroll
        for (int j = 0; j < 8; j++) {
            int cid = t + j * 256;                 // 0..2047
            int row = cid >> 3, c16 = cid & 7;
            uint32_t dsw = sw128((uint32_t)(row * 128 + c16 * 16));
            size_t aoff = (size_t)(m0 + row) * K + kbase + c16 * 8;
            bool ap = (m0 + row) < M;
            cpa16(sb + dsw,           Ahi + aoff, ap);
            cpa16(sb + OFF_ALO + dsw, Alo + aoff, ap);
        }
        // B: 128 rows x 128B, two arrays (1024 chunks each)
#pragma unroll
        for (int j = 0; j < 4; j++) {
            int cid = t + j * 256;                 // 0..1023
            int row = cid >> 3, c16 = cid & 7;
            uint32_t dsw = sw128((uint32_t)(row * 128 + c16 * 16));
            size_t boff = (size_t)(n0 + row) * K + kbase + c16 * 8;
            cpa16(sb + OFF_BHI + dsw, Bhi + boff, true);
            cpa16(sb + OFF_BLO + dsw, Blo + boff, true);
        }
        cpa_commit();
    };

    float acc[4][8][4];
#pragma unroll
    for (int i = 0; i < 4; i++)
#pragma unroll
        for (int j = 0; j < 8; j++)
#pragma unroll
            for (int q = 0; q < 4; q++) acc[i][j][q] = 0.f;

    load_tile(0, 0);
    if (T > 1) load_tile(1, 1); else cpa_commit();

    const int lrow = lid & 15;
    const int lhalf = (lid >> 4) * 16;

    for (int kt = 0; kt < T; kt++) {
        cpa_wait1();
        __syncthreads();
        const uint32_t sb = S + (kt & 1) * STAGE_BYTES;

#pragma unroll
        for (int kk = 0; kk < 4; kk++) {
            const int kb = kk * 32;
            uint32_t ah[4][4], al[4][4], bh[4][4], bl[4][4];
#pragma unroll
            for (int mf = 0; mf < 4; mf++) {
                int row = warp_m * 64 + mf * 16 + lrow;
                uint32_t off = sw128((uint32_t)(row * 128 + kb + lhalf));
                ldsm_x4(ah[mf][0], ah[mf][1], ah[mf][2], ah[mf][3], sb + off);
                ldsm_x4(al[mf][0], al[mf][1], al[mf][2], al[mf][3], sb + OFF_ALO + off);
            }
#pragma unroll
            for (int g = 0; g < 4; g++) {
                int row = warp_n * 64 + g * 16 + lrow;
                uint32_t off = sw128((uint32_t)(row * 128 + kb + lhalf));
                ldsm_x4(bh[g][0], bh[g][1], bh[g][2], bh[g][3], sb + OFF_BHI + off);
                ldsm_x4(bl[g][0], bl[g][1], bl[g][2], bl[g][3], sb + OFF_BLO + off);
            }
            // product-major ordering: acc reuse distance = 32
#pragma unroll
            for (int mf = 0; mf < 4; mf++)
#pragma unroll
                for (int nf = 0; nf < 8; nf++) {
                    int g = nf >> 1, od = nf & 1;
                    mma16816(acc[mf][nf], ah[mf][0], ah[mf][1], ah[mf][2], ah[mf][3],
                             od ? bh[g][1] : bh[g][0], od ? bh[g][3] : bh[g][2]);
                }
#pragma unroll
            for (int mf = 0; mf < 4; mf++)
#pragma unroll
                for (int nf = 0; nf < 8; nf++) {
                    int g = nf >> 1, od = nf & 1;
                    mma16816(acc[mf][nf], ah[mf][0], ah[mf][1], ah[mf][2], ah[mf][3],
                             od ? bl[g][1] : bl[g][0], od ? bl[g][3] : bl[g][2]);
                }
#pragma unroll
            for (int mf = 0; mf < 4; mf++)
#pragma unroll
                for (int nf = 0; nf < 8; nf++) {
                    int g = nf >> 1, od = nf & 1;
                    mma16816(acc[mf][nf], al[mf][0], al[mf][1], al[mf][2], al[mf][3],
                             od ? bh[g][1] : bh[g][0], od ? bh[g][3] : bh[g][2]);
                }
        }
        __syncthreads();
        if (kt + 2 < T) load_tile(kt + 2, kt & 1); else cpa_commit();
    }
    cpa_wait0();

    // ---- epilogue: bias (+relu), C stores, fused column stats partials ----
    float sc16[16], qc16[16];
#pragma unroll
    for (int i = 0; i < 16; i++) { sc16[i] = 0.f; qc16[i] = 0.f; }

#pragma unroll
    for (int mf = 0; mf < 4; mf++) {
        int rbase = m0 + warp_m * 64 + mf * 16 + (lid >> 2);
        bool ok0 = rbase < M, ok1 = rbase + 8 < M;
#pragma unroll
        for (int nf = 0; nf < 8; nf++) {
            int col = n0 + warp_n * 64 + nf * 8 + (lid & 3) * 2;
            float bx = __ldg(&bp[col]), by = __ldg(&bp[col + 1]);
            float v0 = acc[mf][nf][0] + bx, v1 = acc[mf][nf][1] + by;
            float v2 = acc[mf][nf][2] + bx, v3 = acc[mf][nf][3] + by;
            if (reluEpi) {
                v0 = fmaxf(v0, 0.f); v1 = fmaxf(v1, 0.f);
                v2 = fmaxf(v2, 0.f); v3 = fmaxf(v3, 0.f);
            }
            if (ok0) *(float2*)&C[(size_t)rbase * ldc + col]       = make_float2(v0, v1);
            if (ok1) *(float2*)&C[(size_t)(rbase + 8) * ldc + col] = make_float2(v2, v3);
            if (statPart) {
                float a0 = ok0 ? v0 : 0.f, a1 = ok0 ? v1 : 0.f;
                float a2 = ok1 ? v2 : 0.f, a3 = ok1 ? v3 : 0.f;
                sc16[nf * 2 + 0] += a0 + a2;
                qc16[nf * 2 + 0] += a0 * a0 + a2 * a2;
                sc16[nf * 2 + 1] += a1 + a3;
                qc16[nf * 2 + 1] += a1 * a1 + a3 * a3;
            }
        }
    }

    if (statPart) {
#pragma unroll
        for (int i = 0; i < 16; i++) {
#pragma unroll
            for (int off = 4; off <= 16; off <<= 1) {
                sc16[i] += __shfl_xor_sync(0xffffffffu, sc16[i], off);
                qc16[i] += __shfl_xor_sync(0xffffffffu, qc16[i], off);
            }
        }
        float2* red = (float2*)smem;
        if (lid < 4) {
#pragma unroll
            for (int nf = 0; nf < 8; nf++)
#pragma unroll
                for (int b = 0; b < 2; b++) {
                    int col = warp_n * 64 + nf * 8 + lid * 2 + b;
                    red[warp_m * 128 + col] = make_float2(sc16[nf * 2 + b], qc16[nf * 2 + b]);
                }
        }
        __syncthreads();
        if (t < 128) {
            float s = 0.f, q = 0.f;
#pragma unroll
            for (int wm = 0; wm < 4; wm++) {
                float2 p = red[wm * 128 + t];
                s += p.x; q += p.y;
            }
            statPart[(size_t)blockIdx.y * HCW + (size_t)bz * statBzStride + n0 + t] = make_float2(s, q);
        }
    }
}

// ================= split / transpose kernels =================
__global__ void split_kernel(const float* __restrict__ in, bf16* __restrict__ hi,
                             bf16* __restrict__ lo, size_t n)
{
    size_t i = ((size_t)blockIdx.x * blockDim.x + threadIdx.x) * 4;
    if (i >= n) return;
    float4 v = *(const float4*)(in + i);
    bf16 h0 = __float2bfloat16(v.x), h1 = __float2bfloat16(v.y);
    bf16 h2 = __float2bfloat16(v.z), h3 = __float2bfloat16(v.w);
    hi[i] = h0; hi[i+1] = h1; hi[i+2] = h2; hi[i+3] = h3;
    lo[i]   = __float2bfloat16(v.x - __bfloat162float(h0));
    lo[i+1] = __float2bfloat16(v.y - __bfloat162float(h1));
    lo[i+2] = __float2bfloat16(v.z - __bfloat162float(h2));
    lo[i+3] = __float2bfloat16(v.w - __bfloat162float(h3));
}

__global__ void split_affine_kernel(const float* __restrict__ in,
                                    const float* __restrict__ sc, const float* __restrict__ sh,
                                    int ld, bf16* __restrict__ hi, bf16* __restrict__ lo, size_t n)
{
    size_t i = ((size_t)blockIdx.x * blockDim.x + threadIdx.x) * 4;
    if (i >= n) return;
    float4 v = *(const float4*)(in + i);
    int col = (int)(i % ld);
    int soff = (int)(i / ((size_t)ld * NNODE)) * ld + col;
    float4 s = *(const float4*)(sc + soff);
    float4 h = *(const float4*)(sh + soff);
    float w0 = fmaxf(fmaf(v.x, s.x, h.x), 0.f);
    float w1 = fmaxf(fmaf(v.y, s.y, h.y), 0.f);
    float w2 = fmaxf(fmaf(v.z, s.z, h.z), 0.f);
    float w3 = fmaxf(fmaf(v.w, s.w, h.w), 0.f);
    bf16 a0 = __float2bfloat16(w0), a1 = __float2bfloat16(w1);
    bf16 a2 = __float2bfloat16(w2), a3 = __float2bfloat16(w3);
    hi[i] = a0; hi[i+1] = a1; hi[i+2] = a2; hi[i+3] = a3;
    lo[i]   = __float2bfloat16(w0 - __bfloat162float(a0));
    lo[i+1] = __float2bfloat16(w1 - __bfloat162float(a1));
    lo[i+2] = __float2bfloat16(w2 - __bfloat162float(a2));
    lo[i+3] = __float2bfloat16(w3 - __bfloat162float(a3));
}

__global__ void tsplit_kernel(const float* __restrict__ W, long wBatch, int K, int Nn,
                              bf16* __restrict__ hi, bf16* __restrict__ lo, long oBatch)
{
    __shared__ float tile[32][33];
    const float* Wb = W + (long)blockIdx.z * wBatch;
    bf16* hib = hi + (long)blockIdx.z * oBatch;
    bf16* lob = lo + (long)blockIdx.z * oBatch;
    int nb = blockIdx.x * 32, kb = blockIdx.y * 32;
    int tx = threadIdx.x, ty = threadIdx.y;
#pragma unroll
    for (int r = 0; r < 32; r += 8)
        tile[ty + r][tx] = Wb[(size_t)(kb + ty + r) * Nn + nb + tx];
    __syncthreads();
#pragma unroll
    for (int r = 0; r < 32; r += 8) {
        float v = tile[tx][ty + r];
        bf16 h = __float2bfloat16(v);
        size_t o = (size_t)(nb + ty + r) * K + kb + tx;
        hib[o] = h;
        lob[o] = __float2bfloat16(v - __bfloat162float(h));
    }
}

// ================= BN finalize =================
__global__ void finalize_bn_kernel(const float2* __restrict__ part,
                                   const float* __restrict__ g, const float* __restrict__ be,
                                   float* __restrict__ sc, float* __restrict__ sh, float invN)
{
    int i = blockIdx.x * blockDim.x + threadIdx.x;
    float s = 0.f, q = 0.f;
    for (int r = 0; r < MBLK; r++) {
        float2 p = part[(size_t)r * HCW + i];
        s += p.x; q += p.y;
    }
    float mu  = s * invN;
    float var = q * invN - mu * mu;
    float sl = g[i] * rsqrtf(var + EPSBN);
    sc[i] = sl;
    sh[i] = be[i] - mu * sl;
}

// ================= KAN =================
__device__ __forceinline__ void bspline8(float x, float bs[11])
{
#pragma unroll
    for (int j = 0; j < 11; j++) {
        float gl = (float)(j - 3) * 0.4f - 1.0f;
        float gr = (float)(j - 2) * 0.4f - 1.0f;
        bs[j] = (x >= gl && x < gr) ? 1.0f : 0.0f;
    }
#pragma unroll
    for (int p = 1; p <= 3; p++) {
        float inv = 1.0f / (0.4f * (float)p);
#pragma unroll
        for (int j = 0; j < 11 - p; j++) {
            float gj   = (float)(j - 3) * 0.4f - 1.0f;
            float gjp1 = (float)(j + p - 2) * 0.4f - 1.0f;
            bs[j] = ((x - gj) * bs[j] + (gjp1 - x) * bs[j + 1]) * inv;
        }
    }
}

__global__ void __launch_bounds__(256)
kan1_part_kernel(const float* __restrict__ X, const float* __restrict__ bw,
                 const float* __restrict__ sw, const float* __restrict__ sc,
                 float* __restrict__ part, int n)
{
    int node = blockIdx.x * blockDim.x + threadIdx.x;
    int chunk = blockIdx.y;
    if (node >= n) return;
    float acc[KO1];
#pragma unroll
    for (int o = 0; o < KO1; o++) acc[o] = 0.f;

    const int i0 = chunk * (F1D / KCHUNKS);
    for (int ii = 0; ii < F1D / KCHUNKS; ii++) {
        int i = i0 + ii;
        float x = __ldg(&X[(size_t)node * F1D + i]);
        float bs[11];
        bspline8(x, bs);
        float s = x / (1.0f + expf(-x));
#pragma unroll 8
        for (int o = 0; o < KO1; o++) {
            const float4* swp = (const float4*)(sw + ((size_t)o * F1D + i) * 8);
            float4 w0 = __ldg(&swp[0]);
            float4 w1 = __ldg(&swp[1]);
            float sp = bs[0] * w0.x + bs[1] * w0.y + bs[2] * w0.z + bs[3] * w0.w
                     + bs[4] * w1.x + bs[5] * w1.y + bs[6] * w1.z + bs[7] * w1.w;
            acc[o] = fmaf(s, __ldg(&bw[(size_t)o * F1D + i]),
                     fmaf(sp, __ldg(&sc[(size_t)o * F1D + i]), acc[o]));
        }
    }
#pragma unroll
    for (int o = 0; o < KO1; o++)
        part[((size_t)chunk * KO1 + o) * n + node] = acc[o];
}

__global__ void kan1_reduce_kernel(const float* __restrict__ part, float* __restrict__ out, int n)
{
    int gid = blockIdx.x * blockDim.x + threadIdx.x;
    if (gid >= n * KO1) return;
    int node = gid >> 5, o = gid & 31;
    float s = 0.f;
#pragma unroll
    for (int c = 0; c < KCHUNKS; c++)
        s += part[((size_t)c * KO1 + o) * n + node];
    out[(size_t)node * KO1 + o] = s;
}

template <int IN, int OUTC>
__global__ void __launch_bounds__(128)
kan_kernel(const float* __restrict__ X, const float* __restrict__ bw,
           const float* __restrict__ sw, const float* __restrict__ sc,
           float* __restrict__ out, int n)
{
    int node = blockIdx.x * blockDim.x + threadIdx.x;
    if (node >= n) return;
    float acc[OUTC];
#pragma unroll
    for (int o = 0; o < OUTC; o++) acc[o] = 0.f;

    for (int i = 0; i < IN; i++) {
        float x = __ldg(&X[(size_t)node * IN + i]);
        float bs[11];
        bspline8(x, bs);
        float s = x / (1.0f + expf(-x));
#pragma unroll
        for (int o = 0; o < OUTC; o++) {
            const float4* swp = (const float4*)(sw + ((size_t)o * IN + i) * 8);
            float4 w0 = __ldg(&swp[0]);
            float4 w1 = __ldg(&swp[1]);
            float sp = bs[0] * w0.x + bs[1] * w0.y + bs[2] * w0.z + bs[3] * w0.w
                     + bs[4] * w1.x + bs[5] * w1.y + bs[6] * w1.z + bs[7] * w1.w;
            acc[o] = fmaf(s, __ldg(&bw[(size_t)o * IN + i]),
                     fmaf(sp, __ldg(&sc[(size_t)o * IN + i]), acc[o]));
        }
    }
#pragma unroll
    for (int o = 0; o < OUTC; o++) out[(size_t)node * OUTC + o] = acc[o];
}

// ================= launch =================
extern "C" void kernel_launch(void* const* d_in, const int* in_sizes, int n_in,
                              void* d_out, int out_size)
{
    const float* x   = (const float*)d_in[0];
    const float* W1  = (const float*)d_in[3];
    const float* b1  = (const float*)d_in[4];
    const float* gm1 = (const float*)d_in[5];
    const float* bt1 = (const float*)d_in[6];
    const float* W2  = (const float*)d_in[7];
    const float* b2  = (const float*)d_in[8];
    const float* gm2 = (const float*)d_in[9];
    const float* bt2 = (const float*)d_in[10];
    const float* Wf  = (const float*)d_in[11];
    const float* bf  = (const float*)d_in[12];
    const float* bw1 = (const float*)d_in[13];
    const float* sw1 = (const float*)d_in[14];
    const float* sc1 = (const float*)d_in[15];
    const float* bw2 = (const float*)d_in[16];
    const float* sw2 = (const float*)d_in[17];
    const float* sc2 = (const float*)d_in[18];

    float *h1, *hc, *f, *f2, *sca1, *shf1, *sca2, *shf2, *kpart;
    float2 *part;
    bf16 *xhi, *xlo, *h1hi, *h1lo, *hchi, *hclo, *w1hi, *w1lo, *w2hi, *w2lo, *wfhi, *wflo;
    cudaGetSymbolAddress((void**)&h1, g_h1);   cudaGetSymbolAddress((void**)&hc, g_hc);
    cudaGetSymbolAddress((void**)&f, g_f);     cudaGetSymbolAddress((void**)&f2, g_f2);
    cudaGetSymbolAddress((void**)&kpart, g_kpart);
    cudaGetSymbolAddress((void**)&xhi, g_xhi); cudaGetSymbolAddress((void**)&xlo, g_xlo);
    cudaGetSymbolAddress((void**)&h1hi, g_h1hi); cudaGetSymbolAddress((void**)&h1lo, g_h1lo);
    cudaGetSymbolAddress((void**)&hchi, g_hchi); cudaGetSymbolAddress((void**)&hclo, g_hclo);
    cudaGetSymbolAddress((void**)&w1hi, g_w1hi); cudaGetSymbolAddress((void**)&w1lo, g_w1lo);
    cudaGetSymbolAddress((void**)&w2hi, g_w2hi); cudaGetSymbolAddress((void**)&w2lo, g_w2lo);
    cudaGetSymbolAddress((void**)&wfhi, g_wfhi); cudaGetSymbolAddress((void**)&wflo, g_wflo);
    cudaGetSymbolAddress((void**)&part, g_part);
    cudaGetSymbolAddress((void**)&sca1, g_scale1); cudaGetSymbolAddress((void**)&shf1, g_shift1);
    cudaGetSymbolAddress((void**)&sca2, g_scale2); cudaGetSymbolAddress((void**)&shf2, g_shift2);

    cudaFuncSetAttribute(gemm_mma_kernel, cudaFuncAttributeMaxDynamicSharedMemorySize, GEMM_SMEM);

    dim3 tb(32, 8);

    // 1: x -> hi/lo
    {
        size_t n = (size_t)BATCH * NNODE * FEATD;
        split_kernel<<<(unsigned)((n/4 + 255)/256), 256>>>(x, xhi, xlo, n);
    }
    // 2-3: W1, W2 transpose+split
    tsplit_kernel<<<dim3(HDIM/32, FEATD/32, BATCH), tb>>>(W1, (long)FEATD*HDIM, FEATD, HDIM, w1hi, w1lo, (long)HDIM*FEATD);
    tsplit_kernel<<<dim3(HDIM/32, HDIM/32, BATCH), tb>>>(W2, (long)HDIM*HDIM, HDIM, HDIM, w2hi, w2lo, (long)HDIM*HDIM);

    // 4: GEMM1 (+ fused BN1 stats partials)
    gemm_mma_kernel<<<dim3(HDIM/128, MBLK, BATCH), GTHREADS, GEMM_SMEM>>>(
        xhi, xlo, (long)NNODE*FEATD, w1hi, w1lo, (long)HDIM*FEATD,
        b1, HDIM, h1, (long)NNODE*HDIM, HDIM,
        part, HDIM, NNODE, FEATD, 0);

    // 5: Wf transpose+split (independent; overlaps BN1 chain)
    tsplit_kernel<<<dim3(F1D/32, HCW/32, 1), tb>>>(Wf, 0, HCW, F1D, wfhi, wflo, 0);

    // BN1 finalize + affine split
    finalize_bn_kernel<<<HCW/256, 256>>>(part, gm1, bt1, sca1, shf1, 1.0f/NNODE);
    {
        size_t n = (size_t)BATCH * NNODE * HDIM;
        split_affine_kernel<<<(unsigned)((n/4 + 255)/256), 256>>>(h1, sca1, shf1, HDIM, h1hi, h1lo, n);
    }

    // GEMM2 (+ fused BN2 stats partials)
    gemm_mma_kernel<<<dim3(HDIM/128, MBLK, BATCH), GTHREADS, GEMM_SMEM>>>(
        h1hi, h1lo, (long)NNODE*HDIM, w2hi, w2lo, (long)HDIM*HDIM,
        b2, HDIM, hc, (long)HDIM, HCW,
        part, HDIM, NNODE, HDIM, 0);

    // BN2 finalize + affine split
    finalize_bn_kernel<<<HCW/256, 256>>>(part, gm2, bt2, sca2, shf2, 1.0f/NNODE);
    {
        size_t n = (size_t)NNODE * HCW;
        split_affine_kernel<<<(unsigned)((n/4 + 255)/256), 256>>>(hc, sca2, shf2, HCW, hchi, hclo, n);
    }

    // GEMM3 (no stats)
    gemm_mma_kernel<<<dim3(F1D/128, MBLK, 1), GTHREADS, GEMM_SMEM>>>(
        hchi, hclo, 0, wfhi, wflo, 0,
        bf, 0, f, 0, F1D,
        nullptr, 0, NNODE, HCW, 1);

    // KAN layer 1: chunked partials + deterministic reduce
    kan1_part_kernel<<<dim3((NNODE + 255)/256, KCHUNKS), 256>>>(f, bw1, sw1, sc1, kpart, NNODE);
    kan1_reduce_kernel<<<(NNODE * KO1 + 255)/256, 256>>>(kpart, f2, NNODE);

    // KAN layer 2
    kan_kernel<KO1, KO2><<<(NNODE + 127)/128, 128>>>(f2, bw2, sw2, sc2, (float*)d_out, NNODE);
}

// round 16
// speedup vs baseline: 1.1934x; 1.1913x over previous
#include <cuda_runtime.h>
#include <cuda_fp16.h>
#include <math.h>
#include <stdint.h>

#define BATCH 8
#define NNODE 20000
#define FEATD 256
#define HDIM  512
#define HCW   4096
#define F1D   1024
#define KO1   32
#define KO2   10
#define EPSBN 1e-5f
#define KCHUNKS 8
#define BMT 256
#define MBLK ((NNODE + BMT - 1) / BMT)      // 79 m-blocks

typedef __half fp16;

// ---------------- scratch ----------------
__device__ __align__(16) float g_h1[(size_t)BATCH * NNODE * HDIM];
__device__ __align__(16) float g_hc[(size_t)NNODE * HCW];
__device__ __align__(16) float g_f [(size_t)NNODE * F1D];
__device__ __align__(16) float g_f2[(size_t)NNODE * KO1];
__device__ __align__(16) float g_kpart[(size_t)KCHUNKS * KO1 * NNODE];

__device__ __align__(16) fp16 g_xhi[(size_t)BATCH * NNODE * FEATD];
__device__ __align__(16) fp16 g_xlo[(size_t)BATCH * NNODE * FEATD];
__device__ __align__(16) fp16 g_h1hi[(size_t)BATCH * NNODE * HDIM];
__device__ __align__(16) fp16 g_h1lo[(size_t)BATCH * NNODE * HDIM];
__device__ __align__(16) fp16 g_hchi[(size_t)NNODE * HCW];
__device__ __align__(16) fp16 g_hclo[(size_t)NNODE * HCW];
__device__ __align__(16) fp16 g_w1hi[(size_t)BATCH * HDIM * FEATD];
__device__ __align__(16) fp16 g_w2hi[(size_t)BATCH * HDIM * HDIM];
__device__ __align__(16) fp16 g_wfhi[(size_t)F1D * HCW];

__device__ float2 g_part[(size_t)MBLK * HCW];
__device__ float  g_scale1[HCW], g_shift1[HCW];
__device__ float  g_scale2[HCW], g_shift2[HCW];

// ================= PTX helpers (compute_103-safe) =================
__device__ __forceinline__ uint32_t smem_u32(const void* p) {
    uint32_t a;
    asm("{ .reg .u64 t; cvta.to.shared.u64 t, %1; cvt.u32.u64 %0, t; }" : "=r"(a) : "l"(p));
    return a;
}
__device__ __forceinline__ void cpa16(uint32_t dst, const void* src, bool pred) {
    int sz = pred ? 16 : 0;
    asm volatile("cp.async.cg.shared.global [%0], [%1], 16, %2;" :: "r"(dst), "l"(src), "r"(sz) : "memory");
}
__device__ __forceinline__ void cpa_commit() { asm volatile("cp.async.commit_group;" ::: "memory"); }
__device__ __forceinline__ void cpa_wait1() { asm volatile("cp.async.wait_group 1;" ::: "memory"); }
__device__ __forceinline__ void cpa_wait0() { asm volatile("cp.async.wait_group 0;" ::: "memory"); }

__device__ __forceinline__ void ldsm_x4(uint32_t& r0, uint32_t& r1, uint32_t& r2, uint32_t& r3, uint32_t addr) {
    asm volatile("ldmatrix.sync.aligned.m8n8.x4.shared.b16 {%0,%1,%2,%3}, [%4];"
                 : "=r"(r0), "=r"(r1), "=r"(r2), "=r"(r3) : "r"(addr));
}
__device__ __forceinline__ void mma16816(float* c, uint32_t a0, uint32_t a1, uint32_t a2, uint32_t a3,
                                         uint32_t b0, uint32_t b1) {
    asm volatile("mma.sync.aligned.m16n8k16.row.col.f32.f16.f16.f32 "
                 "{%0,%1,%2,%3}, {%4,%5,%6,%7}, {%8,%9}, {%0,%1,%2,%3};"
                 : "+f"(c[0]), "+f"(c[1]), "+f"(c[2]), "+f"(c[3])
                 : "r"(a0), "r"(a1), "r"(a2), "r"(a3), "r"(b0), "r"(b1));
}
static __device__ __forceinline__ uint32_t sw128(uint32_t off) { return off ^ ((off >> 3) & 0x70); }

// ================= HMMA GEMM — CTA 256x128, warp 64x64, asymmetric fp16 2-product =================
// Per kk16: 12 LDSM -> 64 MMA. Stage 80KB (A hi 32K | A lo 32K | B hi 16K), NSTAGE 2.
#define GTHREADS 256
#define KC 64
#define STAGE_BYTES 81920
#define NSTAGE 2
#define GEMM_SMEM (NSTAGE * STAGE_BYTES + 1024)
#define OFF_ALO 32768
#define OFF_BHI 65536

__global__ void __launch_bounds__(GTHREADS, 1)
gemm_mma_kernel(const fp16* __restrict__ Ahi, const fp16* __restrict__ Alo, long aBatch,
                const fp16* __restrict__ Bhi, long bBatch,
                const float* __restrict__ bias, long biasBatch,
                float* __restrict__ C, long cBatch, int ldc,
                float2* __restrict__ statPart, long statBzStride,
                int M, int K, int reluEpi)
{
    extern __shared__ char smem[];
    const uint32_t S = (smem_u32(smem) + 1023) & ~1023u;

    const int bz = blockIdx.z;
    Ahi += (long)bz * aBatch;  Alo += (long)bz * aBatch;
    Bhi += (long)bz * bBatch;
    const float* bp = bias + (long)bz * biasBatch;
    C += (long)bz * cBatch;

    const int n0 = blockIdx.x * 128;
    const int m0 = blockIdx.y * BMT;
    const int t  = threadIdx.x;
    const int wid = t >> 5, lid = t & 31;
    const int warp_m = wid & 3;           // 4 x 64 rows
    const int warp_n = wid >> 2;          // 2 x 64 cols
    const int T = K / KC;

    auto load_tile = [&](int kt, int stg) {
        const uint32_t sb = S + stg * STAGE_BYTES;
        const int kbase = kt * KC;
        // A: 256 rows x 128B, hi+lo (2048 16B chunks each)
#pragma unroll
        for (int j = 0; j < 8; j++) {
            int cid = t + j * 256;
            int row = cid >> 3, c16 = cid & 7;
            uint32_t dsw = sw128((uint32_t)(row * 128 + c16 * 16));
            size_t aoff = (size_t)(m0 + row) * K + kbase + c16 * 8;
            bool ap = (m0 + row) < M;
            cpa16(sb + dsw,           Ahi + aoff, ap);
            cpa16(sb + OFF_ALO + dsw, Alo + aoff, ap);
        }
        // B: 128 rows x 128B, hi only (1024 chunks)
#pragma unroll
        for (int j = 0; j < 4; j++) {
            int cid = t + j * 256;
            int row = cid >> 3, c16 = cid & 7;
            uint32_t dsw = sw128((uint32_t)(row * 128 + c16 * 16));
            size_t boff = (size_t)(n0 + row) * K + kbase + c16 * 8;
            cpa16(sb + OFF_BHI + dsw, Bhi + boff, true);
        }
        cpa_commit();
    };

    float acc[4][8][4];
#pragma unroll
    for (int i = 0; i < 4; i++)
#pragma unroll
        for (int j = 0; j < 8; j++)
#pragma unroll
            for (int q = 0; q < 4; q++) acc[i][j][q] = 0.f;

    load_tile(0, 0);
    if (T > 1) load_tile(1, 1); else cpa_commit();

    const int lrow = lid & 15;
    const int lhalf = (lid >> 4) * 16;

    for (int kt = 0; kt < T; kt++) {
        cpa_wait1();
        __syncthreads();
        const uint32_t sb = S + (kt & 1) * STAGE_BYTES;

#pragma unroll
        for (int kk = 0; kk < 4; kk++) {
            const int kb = kk * 32;
            uint32_t ah[4][4], al[4][4], bh[4][4];
#pragma unroll
            for (int mf = 0; mf < 4; mf++) {
                int row = warp_m * 64 + mf * 16 + lrow;
                uint32_t off = sw128((uint32_t)(row * 128 + kb + lhalf));
                ldsm_x4(ah[mf][0], ah[mf][1], ah[mf][2], ah[mf][3], sb + off);
                ldsm_x4(al[mf][0], al[mf][1], al[mf][2], al[mf][3], sb + OFF_ALO + off);
            }
#pragma unroll
            for (int g = 0; g < 4; g++) {
                int row = warp_n * 64 + g * 16 + lrow;
                uint32_t off = sw128((uint32_t)(row * 128 + kb + lhalf));
                ldsm_x4(bh[g][0], bh[g][1], bh[g][2], bh[g][3], sb + OFF_BHI + off);
            }
            // product-major ordering: acc reuse distance = 32
#pragma unroll
            for (int mf = 0; mf < 4; mf++)
#pragma unroll
                for (int nf = 0; nf < 8; nf++) {
                    int g = nf >> 1, od = nf & 1;
                    mma16816(acc[mf][nf], ah[mf][0], ah[mf][1], ah[mf][2], ah[mf][3],
                             od ? bh[g][1] : bh[g][0], od ? bh[g][3] : bh[g][2]);
                }
#pragma unroll
            for (int mf = 0; mf < 4; mf++)
#pragma unroll
                for (int nf = 0; nf < 8; nf++) {
                    int g = nf >> 1, od = nf & 1;
                    mma16816(acc[mf][nf], al[mf][0], al[mf][1], al[mf][2], al[mf][3],
                             od ? bh[g][1] : bh[g][0], od ? bh[g][3] : bh[g][2]);
                }
        }
        __syncthreads();
        if (kt + 2 < T) load_tile(kt + 2, kt & 1); else cpa_commit();
    }
    cpa_wait0();

    // ---- epilogue: bias (+relu), C stores, fused column stats partials ----
    float sc16[16], qc16[16];
#pragma unroll
    for (int i = 0; i < 16; i++) { sc16[i] = 0.f; qc16[i] = 0.f; }

#pragma unroll
    for (int mf = 0; mf < 4; mf++) {
        int rbase = m0 + warp_m * 64 + mf * 16 + (lid >> 2);
        bool ok0 = rbase < M, ok1 = rbase + 8 < M;
#pragma unroll
        for (int nf = 0; nf < 8; nf++) {
            int col = n0 + warp_n * 64 + nf * 8 + (lid & 3) * 2;
            float bx = __ldg(&bp[col]), by = __ldg(&bp[col + 1]);
            float v0 = acc[mf][nf][0] + bx, v1 = acc[mf][nf][1] + by;
            float v2 = acc[mf][nf][2] + bx, v3 = acc[mf][nf][3] + by;
            if (reluEpi) {
                v0 = fmaxf(v0, 0.f); v1 = fmaxf(v1, 0.f);
                v2 = fmaxf(v2, 0.f); v3 = fmaxf(v3, 0.f);
            }
            if (ok0) *(float2*)&C[(size_t)rbase * ldc + col]       = make_float2(v0, v1);
            if (ok1) *(float2*)&C[(size_t)(rbase + 8) * ldc + col] = make_float2(v2, v3);
            if (statPart) {
                float a0 = ok0 ? v0 : 0.f, a1 = ok0 ? v1 : 0.f;
                float a2 = ok1 ? v2 : 0.f, a3 = ok1 ? v3 : 0.f;
                sc16[nf * 2 + 0] += a0 + a2;
                qc16[nf * 2 + 0] += a0 * a0 + a2 * a2;
                sc16[nf * 2 + 1] += a1 + a3;
                qc16[nf * 2 + 1] += a1 * a1 + a3 * a3;
            }
        }
    }

    if (statPart) {
#pragma unroll
        for (int i = 0; i < 16; i++) {
#pragma unroll
            for (int off = 4; off <= 16; off <<= 1) {
                sc16[i] += __shfl_xor_sync(0xffffffffu, sc16[i], off);
                qc16[i] += __shfl_xor_sync(0xffffffffu, qc16[i], off);
            }
        }
        float2* red = (float2*)smem;
        if (lid < 4) {
#pragma unroll
            for (int nf = 0; nf < 8; nf++)
#pragma unroll
                for (int b = 0; b < 2; b++) {
                    int col = warp_n * 64 + nf * 8 + lid * 2 + b;
                    red[warp_m * 128 + col] = make_float2(sc16[nf * 2 + b], qc16[nf * 2 + b]);
                }
        }
        __syncthreads();
        if (t < 128) {
            float s = 0.f, q = 0.f;
#pragma unroll
            for (int wm = 0; wm < 4; wm++) {
                float2 p = red[wm * 128 + t];
                s += p.x; q += p.y;
            }
            statPart[(size_t)blockIdx.y * HCW + (size_t)bz * statBzStride + n0 + t] = make_float2(s, q);
        }
    }
}

// ================= split / transpose kernels =================
__global__ void split_kernel(const float* __restrict__ in, fp16* __restrict__ hi,
                             fp16* __restrict__ lo, size_t n)
{
    size_t i = ((size_t)blockIdx.x * blockDim.x + threadIdx.x) * 4;
    if (i >= n) return;
    float4 v = *(const float4*)(in + i);
    fp16 h0 = __float2half_rn(v.x), h1 = __float2half_rn(v.y);
    fp16 h2 = __float2half_rn(v.z), h3 = __float2half_rn(v.w);
    hi[i] = h0; hi[i+1] = h1; hi[i+2] = h2; hi[i+3] = h3;
    lo[i]   = __float2half_rn(v.x - __half2float(h0));
    lo[i+1] = __float2half_rn(v.y - __half2float(h1));
    lo[i+2] = __float2half_rn(v.z - __half2float(h2));
    lo[i+3] = __float2half_rn(v.w - __half2float(h3));
}

__global__ void split_affine_kernel(const float* __restrict__ in,
                                    const float* __restrict__ sc, const float* __restrict__ sh,
                                    int ld, fp16* __restrict__ hi, fp16* __restrict__ lo, size_t n)
{
    size_t i = ((size_t)blockIdx.x * blockDim.x + threadIdx.x) * 4;
    if (i >= n) return;
    float4 v = *(const float4*)(in + i);
    int col = (int)(i % ld);
    int soff = (int)(i / ((size_t)ld * NNODE)) * ld + col;
    float4 s = *(const float4*)(sc + soff);
    float4 h = *(const float4*)(sh + soff);
    float w0 = fmaxf(fmaf(v.x, s.x, h.x), 0.f);
    float w1 = fmaxf(fmaf(v.y, s.y, h.y), 0.f);
    float w2 = fmaxf(fmaf(v.z, s.z, h.z), 0.f);
    float w3 = fmaxf(fmaf(v.w, s.w, h.w), 0.f);
    fp16 a0 = __float2half_rn(w0), a1 = __float2half_rn(w1);
    fp16 a2 = __float2half_rn(w2), a3 = __float2half_rn(w3);
    hi[i] = a0; hi[i+1] = a1; hi[i+2] = a2; hi[i+3] = a3;
    lo[i]   = __float2half_rn(w0 - __half2float(a0));
    lo[i+1] = __float2half_rn(w1 - __half2float(a1));
    lo[i+2] = __float2half_rn(w2 - __half2float(a2));
    lo[i+3] = __float2half_rn(w3 - __half2float(a3));
}

// W [K x Nn] -> out [Nn x K], fp16 hi only
__global__ void tsplit_kernel(const float* __restrict__ W, long wBatch, int K, int Nn,
                              fp16* __restrict__ hi, long oBatch)
{
    __shared__ float tile[32][33];
    const float* Wb = W + (long)blockIdx.z * wBatch;
    fp16* hib = hi + (long)blockIdx.z * oBatch;
    int nb = blockIdx.x * 32, kb = blockIdx.y * 32;
    int tx = threadIdx.x, ty = threadIdx.y;
#pragma unroll
    for (int r = 0; r < 32; r += 8)
        tile[ty + r][tx] = Wb[(size_t)(kb + ty + r) * Nn + nb + tx];
    __syncthreads();
#pragma unroll
    for (int r = 0; r < 32; r += 8) {
        float v = tile[tx][ty + r];
        hib[(size_t)(nb + ty + r) * K + kb + tx] = __float2half_rn(v);
    }
}

// ================= BN finalize =================
__global__ void finalize_bn_kernel(const float2* __restrict__ part,
                                   const float* __restrict__ g, const float* __restrict__ be,
                                   float* __restrict__ sc, float* __restrict__ sh, float invN)
{
    int i = blockIdx.x * blockDim.x + threadIdx.x;
    float s = 0.f, q = 0.f;
    for (int r = 0; r < MBLK; r++) {
        float2 p = part[(size_t)r * HCW + i];
        s += p.x; q += p.y;
    }
    float mu  = s * invN;
    float var = q * invN - mu * mu;
    float sl = g[i] * rsqrtf(var + EPSBN);
    sc[i] = sl;
    sh[i] = be[i] - mu * sl;
}

// ================= KAN =================
__device__ __forceinline__ void bspline8(float x, float bs[11])
{
#pragma unroll
    for (int j = 0; j < 11; j++) {
        float gl = (float)(j - 3) * 0.4f - 1.0f;
        float gr = (float)(j - 2) * 0.4f - 1.0f;
        bs[j] = (x >= gl && x < gr) ? 1.0f : 0.0f;
    }
#pragma unroll
    for (int p = 1; p <= 3; p++) {
        float inv = 1.0f / (0.4f * (float)p);
#pragma unroll
        for (int j = 0; j < 11 - p; j++) {
            float gj   = (float)(j - 3) * 0.4f - 1.0f;
            float gjp1 = (float)(j + p - 2) * 0.4f - 1.0f;
            bs[j] = ((x - gj) * bs[j] + (gjp1 - x) * bs[j + 1]) * inv;
        }
    }
}

__global__ void __launch_bounds__(256)
kan1_part_kernel(const float* __restrict__ X, const float* __restrict__ bw,
                 const float* __restrict__ sw, const float* __restrict__ sc,
                 float* __restrict__ part, int n)
{
    int node = blockIdx.x * blockDim.x + threadIdx.x;
    int chunk = blockIdx.y;
    if (node >= n) return;
    float acc[KO1];
#pragma unroll
    for (int o = 0; o < KO1; o++) acc[o] = 0.f;

    const int i0 = chunk * (F1D / KCHUNKS);
    for (int ii = 0; ii < F1D / KCHUNKS; ii++) {
        int i = i0 + ii;
        float x = __ldg(&X[(size_t)node * F1D + i]);
        float bs[11];
        bspline8(x, bs);
        float s = x / (1.0f + expf(-x));
#pragma unroll 8
        for (int o = 0; o < KO1; o++) {
            const float4* swp = (const float4*)(sw + ((size_t)o * F1D + i) * 8);
            float4 w0 = __ldg(&swp[0]);
            float4 w1 = __ldg(&swp[1]);
            float sp = bs[0] * w0.x + bs[1] * w0.y + bs[2] * w0.z + bs[3] * w0.w
                     + bs[4] * w1.x + bs[5] * w1.y + bs[6] * w1.z + bs[7] * w1.w;
            acc[o] = fmaf(s, __ldg(&bw[(size_t)o * F1D + i]),
                     fmaf(sp, __ldg(&sc[(size_t)o * F1D + i]), acc[o]));
        }
    }
#pragma unroll
    for (int o = 0; o < KO1; o++)
        part[((size_t)chunk * KO1 + o) * n + node] = acc[o];
}

__global__ void kan1_reduce_kernel(const float* __restrict__ part, float* __restrict__ out, int n)
{
    int gid = blockIdx.x * blockDim.x + threadIdx.x;
    if (gid >= n * KO1) return;
    int node = gid >> 5, o = gid & 31;
    float s = 0.f;
#pragma unroll
    for (int c = 0; c < KCHUNKS; c++)
        s += part[((size_t)c * KO1 + o) * n + node];
    out[(size_t)node * KO1 + o] = s;
}

template <int IN, int OUTC>
__global__ void __launch_bounds__(128)
kan_kernel(const float* __restrict__ X, const float* __restrict__ bw,
           const float* __restrict__ sw, const float* __restrict__ sc,
           float* __restrict__ out, int n)
{
    int node = blockIdx.x * blockDim.x + threadIdx.x;
    if (node >= n) return;
    float acc[OUTC];
#pragma unroll
    for (int o = 0; o < OUTC; o++) acc[o] = 0.f;

    for (int i = 0; i < IN; i++) {
        float x = __ldg(&X[(size_t)node * IN + i]);
        float bs[11];
        bspline8(x, bs);
        float s = x / (1.0f + expf(-x));
#pragma unroll
        for (int o = 0; o < OUTC; o++) {
            const float4* swp = (const float4*)(sw + ((size_t)o * IN + i) * 8);
            float4 w0 = __ldg(&swp[0]);
            float4 w1 = __ldg(&swp[1]);
            float sp = bs[0] * w0.x + bs[1] * w0.y + bs[2] * w0.z + bs[3] * w0.w
                     + bs[4] * w1.x + bs[5] * w1.y + bs[6] * w1.z + bs[7] * w1.w;
            acc[o] = fmaf(s, __ldg(&bw[(size_t)o * IN + i]),
                     fmaf(sp, __ldg(&sc[(size_t)o * IN + i]), acc[o]));
        }
    }
#pragma unroll
    for (int o = 0; o < OUTC; o++) out[(size_t)node * OUTC + o] = acc[o];
}

// ================= launch =================
extern "C" void kernel_launch(void* const* d_in, const int* in_sizes, int n_in,
                              void* d_out, int out_size)
{
    const float* x   = (const float*)d_in[0];
    const float* W1  = (const float*)d_in[3];
    const float* b1  = (const float*)d_in[4];
    const float* gm1 = (const float*)d_in[5];
    const float* bt1 = (const float*)d_in[6];
    const float* W2  = (const float*)d_in[7];
    const float* b2  = (const float*)d_in[8];
    const float* gm2 = (const float*)d_in[9];
    const float* bt2 = (const float*)d_in[10];
    const float* Wf  = (const float*)d_in[11];
    const float* bf  = (const float*)d_in[12];
    const float* bw1 = (const float*)d_in[13];
    const float* sw1 = (const float*)d_in[14];
    const float* sc1 = (const float*)d_in[15];
    const float* bw2 = (const float*)d_in[16];
    const float* sw2 = (const float*)d_in[17];
    const float* sc2 = (const float*)d_in[18];

    float *h1, *hc, *f, *f2, *sca1, *shf1, *sca2, *shf2, *kpart;
    float2 *part;
    fp16 *xhi, *xlo, *h1hi, *h1lo, *hchi, *hclo, *w1hi, *w2hi, *wfhi;
    cudaGetSymbolAddress((void**)&h1, g_h1);   cudaGetSymbolAddress((void**)&hc, g_hc);
    cudaGetSymbolAddress((void**)&f, g_f);     cudaGetSymbolAddress((void**)&f2, g_f2);
    cudaGetSymbolAddress((void**)&kpart, g_kpart);
    cudaGetSymbolAddress((void**)&xhi, g_xhi); cudaGetSymbolAddress((void**)&xlo, g_xlo);
    cudaGetSymbolAddress((void**)&h1hi, g_h1hi); cudaGetSymbolAddress((void**)&h1lo, g_h1lo);
    cudaGetSymbolAddress((void**)&hchi, g_hchi); cudaGetSymbolAddress((void**)&hclo, g_hclo);
    cudaGetSymbolAddress((void**)&w1hi, g_w1hi);
    cudaGetSymbolAddress((void**)&w2hi, g_w2hi);
    cudaGetSymbolAddress((void**)&wfhi, g_wfhi);
    cudaGetSymbolAddress((void**)&part, g_part);
    cudaGetSymbolAddress((void**)&sca1, g_scale1); cudaGetSymbolAddress((void**)&shf1, g_shift1);
    cudaGetSymbolAddress((void**)&sca2, g_scale2); cudaGetSymbolAddress((void**)&shf2, g_shift2);

    cudaFuncSetAttribute(gemm_mma_kernel, cudaFuncAttributeMaxDynamicSharedMemorySize, GEMM_SMEM);

    dim3 tb(32, 8);

    // 1: x -> hi/lo
    {
        size_t n = (size_t)BATCH * NNODE * FEATD;
        split_kernel<<<(unsigned)((n/4 + 255)/256), 256>>>(x, xhi, xlo, n);
    }
    // 2-3: W1, W2 transpose (fp16 hi only)
    tsplit_kernel<<<dim3(HDIM/32, FEATD/32, BATCH), tb>>>(W1, (long)FEATD*HDIM, FEATD, HDIM, w1hi, (long)HDIM*FEATD);
    tsplit_kernel<<<dim3(HDIM/32, HDIM/32, BATCH), tb>>>(W2, (long)HDIM*HDIM, HDIM, HDIM, w2hi, (long)HDIM*HDIM);

    // 4: GEMM1 (+ fused BN1 stats partials)
    gemm_mma_kernel<<<dim3(HDIM/128, MBLK, BATCH), GTHREADS, GEMM_SMEM>>>(
        xhi, xlo, (long)NNODE*FEATD, w1hi, (long)HDIM*FEATD,
        b1, HDIM, h1, (long)NNODE*HDIM, HDIM,
        part, HDIM, NNODE, FEATD, 0);

    // 5: Wf transpose (overlaps BN1 chain)
    tsplit_kernel<<<dim3(F1D/32, HCW/32, 1), tb>>>(Wf, 0, HCW, F1D, wfhi, 0);

    // BN1 finalize + affine split
    finalize_bn_kernel<<<HCW/256, 256>>>(part, gm1, bt1, sca1, shf1, 1.0f/NNODE);
    {
        size_t n = (size_t)BATCH * NNODE * HDIM;
        split_affine_kernel<<<(unsigned)((n/4 + 255)/256), 256>>>(h1, sca1, shf1, HDIM, h1hi, h1lo, n);
    }

    // GEMM2 (+ fused BN2 stats partials)
    gemm_mma_kernel<<<dim3(HDIM/128, MBLK, BATCH), GTHREADS, GEMM_SMEM>>>(
        h1hi, h1lo, (long)NNODE*HDIM, w2hi, (long)HDIM*HDIM,
        b2, HDIM, hc, (long)HDIM, HCW,
        part, HDIM, NNODE, HDIM, 0);

    // BN2 finalize + affine split
    finalize_bn_kernel<<<HCW/256, 256>>>(part, gm2, bt2, sca2, shf2, 1.0f/NNODE);
    {
        size_t n = (size_t)NNODE * HCW;
        split_affine_kernel<<<(unsigned)((n/4 + 255)/256), 256>>>(hc, sca2, shf2, HCW, hchi, hclo, n);
    }

    // GEMM3 (no stats)
    gemm_mma_kernel<<<dim3(F1D/128, MBLK, 1), GTHREADS, GEMM_SMEM>>>(
        hchi, hclo, 0, wfhi, 0,
        bf, 0, f, 0, F1D,
        nullptr, 0, NNODE, HCW, 1);

    // KAN layer 1: chunked partials + deterministic reduce
    kan1_part_kernel<<<dim3((NNODE + 255)/256, KCHUNKS), 256>>>(f, bw1, sw1, sc1, kpart, NNODE);
    kan1_reduce_kernel<<<(NNODE * KO1 + 255)/256, 256>>>(kpart, f2, NNODE);

    // KAN layer 2
    kan_kernel<KO1, KO2><<<(NNODE + 127)/128, 128>>>(f2, bw2, sw2, sc2, (float*)d_out, NNODE);
}

// round 17
// speedup vs baseline: 1.3591x; 1.1389x over previous
#include <cuda_runtime.h>
#include <cuda_fp16.h>
#include <math.h>
#include <stdint.h>

#define BATCH 8
#define NNODE 20000
#define FEATD 256
#define HDIM  512
#define HCW   4096
#define F1D   1024
#define KO1   32
#define KO2   10
#define EPSBN 1e-5f
#define KCHUNKS 8
#define BMT 256
#define MBLK ((NNODE + BMT - 1) / BMT)      // 79 m-blocks

typedef __half fp16;

// ---------------- scratch ----------------
__device__ __align__(16) float g_f [(size_t)NNODE * F1D];
__device__ __align__(16) float g_f2[(size_t)NNODE * KO1];
__device__ __align__(16) float g_kpart[(size_t)KCHUNKS * KO1 * NNODE];

__device__ __align__(16) fp16 g_xhi[(size_t)BATCH * NNODE * FEATD];
__device__ __align__(16) fp16 g_xlo[(size_t)BATCH * NNODE * FEATD];
__device__ __align__(16) fp16 g_h1hi[(size_t)BATCH * NNODE * HDIM];
__device__ __align__(16) fp16 g_h1lo[(size_t)BATCH * NNODE * HDIM];
__device__ __align__(16) fp16 g_hchi[(size_t)NNODE * HCW];
__device__ __align__(16) fp16 g_hclo[(size_t)NNODE * HCW];
__device__ __align__(16) fp16 g_w1hi[(size_t)BATCH * HDIM * FEATD];
__device__ __align__(16) fp16 g_w2hi[(size_t)BATCH * HDIM * HDIM];
__device__ __align__(16) fp16 g_wfhi[(size_t)F1D * HCW];

__device__ __align__(16) float g_swp[(size_t)KO1 * F1D * 8];   // sw1 * sc1
__device__ __align__(16) float g_bwT[(size_t)F1D * KO1];        // bw1 transposed [i][o]

__device__ float2 g_part[(size_t)MBLK * HCW];
__device__ float  g_scale1[HCW], g_shift1[HCW];
__device__ float  g_scale2[HCW], g_shift2[HCW];

// ================= PTX helpers (compute_103-safe) =================
__device__ __forceinline__ uint32_t smem_u32(const void* p) {
    uint32_t a;
    asm("{ .reg .u64 t; cvta.to.shared.u64 t, %1; cvt.u32.u64 %0, t; }" : "=r"(a) : "l"(p));
    return a;
}
__device__ __forceinline__ void cpa16(uint32_t dst, const void* src, bool pred) {
    int sz = pred ? 16 : 0;
    asm volatile("cp.async.cg.shared.global [%0], [%1], 16, %2;" :: "r"(dst), "l"(src), "r"(sz) : "memory");
}
__device__ __forceinline__ void cpa_commit() { asm volatile("cp.async.commit_group;" ::: "memory"); }
__device__ __forceinline__ void cpa_wait1() { asm volatile("cp.async.wait_group 1;" ::: "memory"); }
__device__ __forceinline__ void cpa_wait0() { asm volatile("cp.async.wait_group 0;" ::: "memory"); }

__device__ __forceinline__ void ldsm_x4(uint32_t& r0, uint32_t& r1, uint32_t& r2, uint32_t& r3, uint32_t addr) {
    asm volatile("ldmatrix.sync.aligned.m8n8.x4.shared.b16 {%0,%1,%2,%3}, [%4];"
                 : "=r"(r0), "=r"(r1), "=r"(r2), "=r"(r3) : "r"(addr));
}
__device__ __forceinline__ void mma16816(float* c, uint32_t a0, uint32_t a1, uint32_t a2, uint32_t a3,
                                         uint32_t b0, uint32_t b1) {
    asm volatile("mma.sync.aligned.m16n8k16.row.col.f32.f16.f16.f32 "
                 "{%0,%1,%2,%3}, {%4,%5,%6,%7}, {%8,%9}, {%0,%1,%2,%3};"
                 : "+f"(c[0]), "+f"(c[1]), "+f"(c[2]), "+f"(c[3])
                 : "r"(a0), "r"(a1), "r"(a2), "r"(a3), "r"(b0), "r"(b1));
}
static __device__ __forceinline__ uint32_t sw128(uint32_t off) { return off ^ ((off >> 3) & 0x70); }

// ================= HMMA GEMM — CTA 256x128, warp 64x64, asymmetric fp16 2-product =================
#define GTHREADS 256
#define KC 64
#define STAGE_BYTES 81920
#define NSTAGE 2
#define GEMM_SMEM (NSTAGE * STAGE_BYTES + 1024)
#define OFF_ALO 32768
#define OFF_BHI 65536

__global__ void __launch_bounds__(GTHREADS, 1)
gemm_mma_kernel(const fp16* __restrict__ Ahi, const fp16* __restrict__ Alo, long aBatch,
                const fp16* __restrict__ Bhi, long bBatch,
                const float* __restrict__ bias, long biasBatch,
                float* __restrict__ Cf, fp16* __restrict__ Chi, fp16* __restrict__ Clo,
                long cBatch, int ldc,
                float2* __restrict__ statPart, long statBzStride,
                int M, int K, int reluEpi)
{
    extern __shared__ char smem[];
    const uint32_t S = (smem_u32(smem) + 1023) & ~1023u;

    const int bz = blockIdx.z;
    Ahi += (long)bz * aBatch;  Alo += (long)bz * aBatch;
    Bhi += (long)bz * bBatch;
    const float* bp = bias + (long)bz * biasBatch;
    if (Cf)  Cf  += (long)bz * cBatch;
    if (Chi) { Chi += (long)bz * cBatch; Clo += (long)bz * cBatch; }

    const int n0 = blockIdx.x * 128;
    const int m0 = blockIdx.y * BMT;
    const int t  = threadIdx.x;
    const int wid = t >> 5, lid = t & 31;
    const int warp_m = wid & 3;
    const int warp_n = wid >> 2;
    const int T = K / KC;

    auto load_tile = [&](int kt, int stg) {
        const uint32_t sb = S + stg * STAGE_BYTES;
        const int kbase = kt * KC;
#pragma unroll
        for (int j = 0; j < 8; j++) {
            int cid = t + j * 256;
            int row = cid >> 3, c16 = cid & 7;
            uint32_t dsw = sw128((uint32_t)(row * 128 + c16 * 16));
            size_t aoff = (size_t)(m0 + row) * K + kbase + c16 * 8;
            bool ap = (m0 + row) < M;
            cpa16(sb + dsw,           Ahi + aoff, ap);
            cpa16(sb + OFF_ALO + dsw, Alo + aoff, ap);
        }
#pragma unroll
        for (int j = 0; j < 4; j++) {
            int cid = t + j * 256;
            int row = cid >> 3, c16 = cid & 7;
            uint32_t dsw = sw128((uint32_t)(row * 128 + c16 * 16));
            size_t boff = (size_t)(n0 + row) * K + kbase + c16 * 8;
            cpa16(sb + OFF_BHI + dsw, Bhi + boff, true);
        }
        cpa_commit();
    };

    float acc[4][8][4];
#pragma unroll
    for (int i = 0; i < 4; i++)
#pragma unroll
        for (int j = 0; j < 8; j++)
#pragma unroll
            for (int q = 0; q < 4; q++) acc[i][j][q] = 0.f;

    load_tile(0, 0);
    if (T > 1) load_tile(1, 1); else cpa_commit();

    const int lrow = lid & 15;
    const int lhalf = (lid >> 4) * 16;

    for (int kt = 0; kt < T; kt++) {
        cpa_wait1();
        __syncthreads();
        const uint32_t sb = S + (kt & 1) * STAGE_BYTES;

#pragma unroll
        for (int kk = 0; kk < 4; kk++) {
            const int kb = kk * 32;
            uint32_t ah[4][4], al[4][4], bh[4][4];
#pragma unroll
            for (int mf = 0; mf < 4; mf++) {
                int row = warp_m * 64 + mf * 16 + lrow;
                uint32_t off = sw128((uint32_t)(row * 128 + kb + lhalf));
                ldsm_x4(ah[mf][0], ah[mf][1], ah[mf][2], ah[mf][3], sb + off);
                ldsm_x4(al[mf][0], al[mf][1], al[mf][2], al[mf][3], sb + OFF_ALO + off);
            }
#pragma unroll
            for (int g = 0; g < 4; g++) {
                int row = warp_n * 64 + g * 16 + lrow;
                uint32_t off = sw128((uint32_t)(row * 128 + kb + lhalf));
                ldsm_x4(bh[g][0], bh[g][1], bh[g][2], bh[g][3], sb + OFF_BHI + off);
            }
#pragma unroll
            for (int mf = 0; mf < 4; mf++)
#pragma unroll
                for (int nf = 0; nf < 8; nf++) {
                    int g = nf >> 1, od = nf & 1;
                    mma16816(acc[mf][nf], ah[mf][0], ah[mf][1], ah[mf][2], ah[mf][3],
                             od ? bh[g][1] : bh[g][0], od ? bh[g][3] : bh[g][2]);
                }
#pragma unroll
            for (int mf = 0; mf < 4; mf++)
#pragma unroll
                for (int nf = 0; nf < 8; nf++) {
                    int g = nf >> 1, od = nf & 1;
                    mma16816(acc[mf][nf], al[mf][0], al[mf][1], al[mf][2], al[mf][3],
                             od ? bh[g][1] : bh[g][0], od ? bh[g][3] : bh[g][2]);
                }
        }
        __syncthreads();
        if (kt + 2 < T) load_tile(kt + 2, kt & 1); else cpa_commit();
    }
    cpa_wait0();

    // ---- epilogue: bias (+relu), stores (fp32 or fp16 hi/lo), fused column stats ----
    float sc16[16], qc16[16];
#pragma unroll
    for (int i = 0; i < 16; i++) { sc16[i] = 0.f; qc16[i] = 0.f; }

#pragma unroll
    for (int mf = 0; mf < 4; mf++) {
        int rbase = m0 + warp_m * 64 + mf * 16 + (lid >> 2);
        bool ok0 = rbase < M, ok1 = rbase + 8 < M;
#pragma unroll
        for (int nf = 0; nf < 8; nf++) {
            int col = n0 + warp_n * 64 + nf * 8 + (lid & 3) * 2;
            float bx = __ldg(&bp[col]), by = __ldg(&bp[col + 1]);
            float v0 = acc[mf][nf][0] + bx, v1 = acc[mf][nf][1] + by;
            float v2 = acc[mf][nf][2] + bx, v3 = acc[mf][nf][3] + by;
            if (reluEpi) {
                v0 = fmaxf(v0, 0.f); v1 = fmaxf(v1, 0.f);
                v2 = fmaxf(v2, 0.f); v3 = fmaxf(v3, 0.f);
            }
            if (Chi) {
                fp16 h0 = __float2half_rn(v0), h1 = __float2half_rn(v1);
                fp16 h2 = __float2half_rn(v2), h3 = __float2half_rn(v3);
                if (ok0) {
                    *(__half2*)&Chi[(size_t)rbase * ldc + col] = __halves2half2(h0, h1);
                    *(__half2*)&Clo[(size_t)rbase * ldc + col] =
                        __halves2half2(__float2half_rn(v0 - __half2float(h0)),
                                       __float2half_rn(v1 - __half2float(h1)));
                }
                if (ok1) {
                    *(__half2*)&Chi[(size_t)(rbase + 8) * ldc + col] = __halves2half2(h2, h3);
                    *(__half2*)&Clo[(size_t)(rbase + 8) * ldc + col] =
                        __halves2half2(__float2half_rn(v2 - __half2float(h2)),
                                       __float2half_rn(v3 - __half2float(h3)));
                }
            } else {
                if (ok0) *(float2*)&Cf[(size_t)rbase * ldc + col]       = make_float2(v0, v1);
                if (ok1) *(float2*)&Cf[(size_t)(rbase + 8) * ldc + col] = make_float2(v2, v3);
            }
            if (statPart) {
                float a0 = ok0 ? v0 : 0.f, a1 = ok0 ? v1 : 0.f;
                float a2 = ok1 ? v2 : 0.f, a3 = ok1 ? v3 : 0.f;
                sc16[nf * 2 + 0] += a0 + a2;
                qc16[nf * 2 + 0] += a0 * a0 + a2 * a2;
                sc16[nf * 2 + 1] += a1 + a3;
                qc16[nf * 2 + 1] += a1 * a1 + a3 * a3;
            }
        }
    }

    if (statPart) {
#pragma unroll
        for (int i = 0; i < 16; i++) {
#pragma unroll
            for (int off = 4; off <= 16; off <<= 1) {
                sc16[i] += __shfl_xor_sync(0xffffffffu, sc16[i], off);
                qc16[i] += __shfl_xor_sync(0xffffffffu, qc16[i], off);
            }
        }
        float2* red = (float2*)smem;
        if (lid < 4) {
#pragma unroll
            for (int nf = 0; nf < 8; nf++)
#pragma unroll
                for (int b = 0; b < 2; b++) {
                    int col = warp_n * 64 + nf * 8 + lid * 2 + b;
                    red[warp_m * 128 + col] = make_float2(sc16[nf * 2 + b], qc16[nf * 2 + b]);
                }
        }
        __syncthreads();
        if (t < 128) {
            float s = 0.f, q = 0.f;
#pragma unroll
            for (int wm = 0; wm < 4; wm++) {
                float2 p = red[wm * 128 + t];
                s += p.x; q += p.y;
            }
            statPart[(size_t)blockIdx.y * HCW + (size_t)bz * statBzStride + n0 + t] = make_float2(s, q);
        }
    }
}

// ================= split / transpose / resplit kernels =================
__global__ void split_kernel(const float* __restrict__ in, fp16* __restrict__ hi,
                             fp16* __restrict__ lo, size_t n)
{
    size_t i = ((size_t)blockIdx.x * blockDim.x + threadIdx.x) * 4;
    if (i >= n) return;
    float4 v = *(const float4*)(in + i);
    fp16 h0 = __float2half_rn(v.x), h1 = __float2half_rn(v.y);
    fp16 h2 = __float2half_rn(v.z), h3 = __float2half_rn(v.w);
    hi[i] = h0; hi[i+1] = h1; hi[i+2] = h2; hi[i+3] = h3;
    lo[i]   = __float2half_rn(v.x - __half2float(h0));
    lo[i+1] = __float2half_rn(v.y - __half2float(h1));
    lo[i+2] = __float2half_rn(v.z - __half2float(h2));
    lo[i+3] = __float2half_rn(v.w - __half2float(h3));
}

// In-place: v = hi+lo; w = relu(v*scale+shift); re-split w into hi/lo.
__global__ void affine_resplit_kernel(fp16* __restrict__ hi, fp16* __restrict__ lo,
                                      const float* __restrict__ sc, const float* __restrict__ sh,
                                      int ld, size_t n)
{
    size_t i = ((size_t)blockIdx.x * blockDim.x + threadIdx.x) * 4;
    if (i >= n) return;
    __half2 hv0 = *(__half2*)&hi[i], hv1 = *(__half2*)&hi[i + 2];
    __half2 lv0 = *(__half2*)&lo[i], lv1 = *(__half2*)&lo[i + 2];
    int col = (int)(i % ld);
    int soff = (int)(i / ((size_t)ld * NNODE)) * ld + col;
    float4 s = *(const float4*)(sc + soff);
    float4 h = *(const float4*)(sh + soff);
    float v0 = __half2float(__low2half(hv0))  + __half2float(__low2half(lv0));
    float v1 = __half2float(__high2half(hv0)) + __half2float(__high2half(lv0));
    float v2 = __half2float(__low2half(hv1))  + __half2float(__low2half(lv1));
    float v3 = __half2float(__high2half(hv1)) + __half2float(__high2half(lv1));
    float w0 = fmaxf(fmaf(v0, s.x, h.x), 0.f);
    float w1 = fmaxf(fmaf(v1, s.y, h.y), 0.f);
    float w2 = fmaxf(fmaf(v2, s.z, h.z), 0.f);
    float w3 = fmaxf(fmaf(v3, s.w, h.w), 0.f);
    fp16 a0 = __float2half_rn(w0), a1 = __float2half_rn(w1);
    fp16 a2 = __float2half_rn(w2), a3 = __float2half_rn(w3);
    *(__half2*)&hi[i]     = __halves2half2(a0, a1);
    *(__half2*)&hi[i + 2] = __halves2half2(a2, a3);
    *(__half2*)&lo[i]     = __halves2half2(__float2half_rn(w0 - __half2float(a0)),
                                           __float2half_rn(w1 - __half2float(a1)));
    *(__half2*)&lo[i + 2] = __halves2half2(__float2half_rn(w2 - __half2float(a2)),
                                           __float2half_rn(w3 - __half2float(a3)));
}

__global__ void tsplit_kernel(const float* __restrict__ W, long wBatch, int K, int Nn,
                              fp16* __restrict__ hi, long oBatch)
{
    __shared__ float tile[32][33];
    const float* Wb = W + (long)blockIdx.z * wBatch;
    fp16* hib = hi + (long)blockIdx.z * oBatch;
    int nb = blockIdx.x * 32, kb = blockIdx.y * 32;
    int tx = threadIdx.x, ty = threadIdx.y;
#pragma unroll
    for (int r = 0; r < 32; r += 8)
        tile[ty + r][tx] = Wb[(size_t)(kb + ty + r) * Nn + nb + tx];
    __syncthreads();
#pragma unroll
    for (int r = 0; r < 32; r += 8) {
        float v = tile[tx][ty + r];
        hib[(size_t)(nb + ty + r) * K + kb + tx] = __float2half_rn(v);
    }
}

// ================= KAN prep: sw*sc premultiply, bw transpose =================
__global__ void kan_prep_kernel(const float* __restrict__ sw, const float* __restrict__ sc,
                                const float* __restrict__ bw,
                                float* __restrict__ swp, float* __restrict__ bwT)
{
    int g = blockIdx.x * blockDim.x + threadIdx.x;
    if (g < KO1 * F1D * 8)
        swp[g] = sw[g] * sc[g >> 3];
    if (g < KO1 * F1D) {
        int o = g / F1D, i = g % F1D;
        bwT[(size_t)i * KO1 + o] = bw[g];
    }
}

// ================= BN finalize =================
__global__ void finalize_bn_kernel(const float2* __restrict__ part,
                                   const float* __restrict__ g, const float* __restrict__ be,
                                   float* __restrict__ sc, float* __restrict__ sh, float invN)
{
    int i = blockIdx.x * blockDim.x + threadIdx.x;
    float s = 0.f, q = 0.f;
    for (int r = 0; r < MBLK; r++) {
        float2 p = part[(size_t)r * HCW + i];
        s += p.x; q += p.y;
    }
    float mu  = s * invN;
    float var = q * invN - mu * mu;
    float sl = g[i] * rsqrtf(var + EPSBN);
    sc[i] = sl;
    sh[i] = be[i] - mu * sl;
}

// ================= KAN =================
__device__ __forceinline__ void bspline8(float x, float bs[11])
{
#pragma unroll
    for (int j = 0; j < 11; j++) {
        float gl = (float)(j - 3) * 0.4f - 1.0f;
        float gr = (float)(j - 2) * 0.4f - 1.0f;
        bs[j] = (x >= gl && x < gr) ? 1.0f : 0.0f;
    }
#pragma unroll
    for (int p = 1; p <= 3; p++) {
        float inv = 1.0f / (0.4f * (float)p);
#pragma unroll
        for (int j = 0; j < 11 - p; j++) {
            float gj   = (float)(j - 3) * 0.4f - 1.0f;
            float gjp1 = (float)(j + p - 2) * 0.4f - 1.0f;
            bs[j] = ((x - gj) * bs[j] + (gjp1 - x) * bs[j + 1]) * inv;
        }
    }
}

__global__ void __launch_bounds__(256)
kan1_part_kernel(const float* __restrict__ X, const float* __restrict__ bwT,
                 const float* __restrict__ swp,
                 float* __restrict__ part, int n)
{
    int node = blockIdx.x * blockDim.x + threadIdx.x;
    int chunk = blockIdx.y;
    if (node >= n) return;
    float acc[KO1];
#pragma unroll
    for (int o = 0; o < KO1; o++) acc[o] = 0.f;

    const int i0 = chunk * (F1D / KCHUNKS);
    for (int ii = 0; ii < F1D / KCHUNKS; ii++) {
        int i = i0 + ii;
        float x = __ldg(&X[(size_t)node * F1D + i]);
        float bs[11];
        bspline8(x, bs);
        float s = x / (1.0f + expf(-x));
        float bwv[KO1];
        const float4* bwp = (const float4*)(bwT + (size_t)i * KO1);
#pragma unroll
        for (int q = 0; q < KO1 / 4; q++) ((float4*)bwv)[q] = __ldg(&bwp[q]);
#pragma unroll 8
        for (int o = 0; o < KO1; o++) {
            const float4* swq = (const float4*)(swp + ((size_t)o * F1D + i) * 8);
            float4 w0 = __ldg(&swq[0]);
            float4 w1 = __ldg(&swq[1]);
            float sp = bs[0] * w0.x + bs[1] * w0.y + bs[2] * w0.z + bs[3] * w0.w
                     + bs[4] * w1.x + bs[5] * w1.y + bs[6] * w1.z + bs[7] * w1.w;
            acc[o] = fmaf(s, bwv[o], acc[o]) + sp;
        }
    }
#pragma unroll
    for (int o = 0; o < KO1; o++)
        part[((size_t)chunk * KO1 + o) * n + node] = acc[o];
}

__global__ void kan1_reduce_kernel(const float* __restrict__ part, float* __restrict__ out, int n)
{
    int gid = blockIdx.x * blockDim.x + threadIdx.x;
    if (gid >= n * KO1) return;
    int node = gid >> 5, o = gid & 31;
    float s = 0.f;
#pragma unroll
    for (int c = 0; c < KCHUNKS; c++)
        s += part[((size_t)c * KO1 + o) * n + node];
    out[(size_t)node * KO1 + o] = s;
}

template <int IN, int OUTC>
__global__ void __launch_bounds__(128)
kan_kernel(const float* __restrict__ X, const float* __restrict__ bw,
           const float* __restrict__ sw, const float* __restrict__ sc,
           float* __restrict__ out, int n)
{
    int node = blockIdx.x * blockDim.x + threadIdx.x;
    if (node >= n) return;
    float acc[OUTC];
#pragma unroll
    for (int o = 0; o < OUTC; o++) acc[o] = 0.f;

    for (int i = 0; i < IN; i++) {
        float x = __ldg(&X[(size_t)node * IN + i]);
        float bs[11];
        bspline8(x, bs);
        float s = x / (1.0f + expf(-x));
#pragma unroll
        for (int o = 0; o < OUTC; o++) {
            const float4* swq = (const float4*)(sw + ((size_t)o * IN + i) * 8);
            float4 w0 = __ldg(&swq[0]);
            float4 w1 = __ldg(&swq[1]);
            float sp = bs[0] * w0.x + bs[1] * w0.y + bs[2] * w0.z + bs[3] * w0.w
                     + bs[4] * w1.x + bs[5] * w1.y + bs[6] * w1.z + bs[7] * w1.w;
            acc[o] = fmaf(s, __ldg(&bw[(size_t)o * IN + i]),
                     fmaf(sp, __ldg(&sc[(size_t)o * IN + i]), acc[o]));
        }
    }
#pragma unroll
    for (int o = 0; o < OUTC; o++) out[(size_t)node * OUTC + o] = acc[o];
}

// ================= launch =================
extern "C" void kernel_launch(void* const* d_in, const int* in_sizes, int n_in,
                              void* d_out, int out_size)
{
    const float* x   = (const float*)d_in[0];
    const float* W1  = (const float*)d_in[3];
    const float* b1  = (const float*)d_in[4];
    const float* gm1 = (const float*)d_in[5];
    const float* bt1 = (const float*)d_in[6];
    const float* W2  = (const float*)d_in[7];
    const float* b2  = (const float*)d_in[8];
    const float* gm2 = (const float*)d_in[9];
    const float* bt2 = (const float*)d_in[10];
    const float* Wf  = (const float*)d_in[11];
    const float* bf  = (const float*)d_in[12];
    const float* bw1 = (const float*)d_in[13];
    const float* sw1 = (const float*)d_in[14];
    const float* sc1 = (const float*)d_in[15];
    const float* bw2 = (const float*)d_in[16];
    const float* sw2 = (const float*)d_in[17];
    const float* sc2 = (const float*)d_in[18];

    float *f, *f2, *sca1, *shf1, *sca2, *shf2, *kpart, *swp, *bwT;
    float2 *part;
    fp16 *xhi, *xlo, *h1hi, *h1lo, *hchi, *hclo, *w1hi, *w2hi, *wfhi;
    cudaGetSymbolAddress((void**)&f, g_f);     cudaGetSymbolAddress((void**)&f2, g_f2);
    cudaGetSymbolAddress((void**)&kpart, g_kpart);
    cudaGetSymbolAddress((void**)&swp, g_swp); cudaGetSymbolAddress((void**)&bwT, g_bwT);
    cudaGetSymbolAddress((void**)&xhi, g_xhi); cudaGetSymbolAddress((void**)&xlo, g_xlo);
    cudaGetSymbolAddress((void**)&h1hi, g_h1hi); cudaGetSymbolAddress((void**)&h1lo, g_h1lo);
    cudaGetSymbolAddress((void**)&hchi, g_hchi); cudaGetSymbolAddress((void**)&hclo, g_hclo);
    cudaGetSymbolAddress((void**)&w1hi, g_w1hi);
    cudaGetSymbolAddress((void**)&w2hi, g_w2hi);
    cudaGetSymbolAddress((void**)&wfhi, g_wfhi);
    cudaGetSymbolAddress((void**)&part, g_part);
    cudaGetSymbolAddress((void**)&sca1, g_scale1); cudaGetSymbolAddress((void**)&shf1, g_shift1);
    cudaGetSymbolAddress((void**)&sca2, g_scale2); cudaGetSymbolAddress((void**)&shf2, g_shift2);

    cudaFuncSetAttribute(gemm_mma_kernel, cudaFuncAttributeMaxDynamicSharedMemorySize, GEMM_SMEM);

    dim3 tb(32, 8);

    // x -> hi/lo
    {
        size_t n = (size_t)BATCH * NNODE * FEATD;
        split_kernel<<<(unsigned)((n/4 + 255)/256), 256>>>(x, xhi, xlo, n);
    }
    // W1, W2 transpose (fp16 hi)
    tsplit_kernel<<<dim3(HDIM/32, FEATD/32, BATCH), tb>>>(W1, (long)FEATD*HDIM, FEATD, HDIM, w1hi, (long)HDIM*FEATD);
    tsplit_kernel<<<dim3(HDIM/32, HDIM/32, BATCH), tb>>>(W2, (long)HDIM*HDIM, HDIM, HDIM, w2hi, (long)HDIM*HDIM);

    // GEMM1 -> h1 (fp16 hi/lo) + fused BN1 stats
    gemm_mma_kernel<<<dim3(HDIM/128, MBLK, BATCH), GTHREADS, GEMM_SMEM>>>(
        xhi, xlo, (long)NNODE*FEATD, w1hi, (long)HDIM*FEATD,
        b1, HDIM, nullptr, h1hi, h1lo, (long)NNODE*HDIM, HDIM,
        part, HDIM, NNODE, FEATD, 0);

    // overlap: Wf transpose + KAN prep
    tsplit_kernel<<<dim3(F1D/32, HCW/32, 1), tb>>>(Wf, 0, HCW, F1D, wfhi, 0);
    kan_prep_kernel<<<(KO1*F1D*8 + 255)/256, 256>>>(sw1, sc1, bw1, swp, bwT);

    // BN1 finalize + in-place affine resplit
    finalize_bn_kernel<<<HCW/256, 256>>>(part, gm1, bt1, sca1, shf1, 1.0f/NNODE);
    {
        size_t n = (size_t)BATCH * NNODE * HDIM;
        affine_resplit_kernel<<<(unsigned)((n/4 + 255)/256), 256>>>(h1hi, h1lo, sca1, shf1, HDIM, n);
    }

    // GEMM2 -> hc (fp16 hi/lo) + fused BN2 stats
    gemm_mma_kernel<<<dim3(HDIM/128, MBLK, BATCH), GTHREADS, GEMM_SMEM>>>(
        h1hi, h1lo, (long)NNODE*HDIM, w2hi, (long)HDIM*HDIM,
        b2, HDIM, nullptr, hchi, hclo, (long)HDIM, HCW,
        part, HDIM, NNODE, HDIM, 0);

    // BN2 finalize + in-place affine resplit
    finalize_bn_kernel<<<HCW/256, 256>>>(part, gm2, bt2, sca2, shf2, 1.0f/NNODE);
    {
        size_t n = (size_t)NNODE * HCW;
        affine_resplit_kernel<<<(unsigned)((n/4 + 255)/256), 256>>>(hchi, hclo, sca2, shf2, HCW, n);
    }

    // GEMM3 -> f (fp32)
    gemm_mma_kernel<<<dim3(F1D/128, MBLK, 1), GTHREADS, GEMM_SMEM>>>(
        hchi, hclo, 0, wfhi, 0,
        bf, 0, f, nullptr, nullptr, 0, F1D,
        nullptr, 0, NNODE, HCW, 1);

    // KAN layer 1: chunked partials + deterministic reduce
    kan1_part_kernel<<<dim3((NNODE + 255)/256, KCHUNKS), 256>>>(f, bwT, swp, kpart, NNODE);
    kan1_reduce_kernel<<<(NNODE * KO1 + 255)/256, 256>>>(kpart, f2, NNODE);

    // KAN layer 2
    kan_kernel<KO1, KO2><<<(NNODE + 127)/128, 128>>>(f2, bw2, sw2, sc2, (float*)d_out, NNODE);
}